// round 12
// baseline (speedup 1.0000x reference)
#include <cuda_runtime.h>
#include <cuda_fp16.h>

#define B_  16
#define C_  256
#define HW_ 1024
#define NSPLIT 2

// ---- device scratch (no allocations allowed) ----
__device__ __half g_wh[512 * C_];        // weights [m][k]: m<256 K, else Q
__device__ __half g_kh[B_ * HW_ * C_];   // normalized keys    [b][n][c]
__device__ __half g_qh[B_ * HW_ * C_];   // normalized queries [b][m][c]
__device__ float g_bias[512];
__device__ float g_v[B_ * HW_];            // value scalars
__device__ float g_G[B_ * HW_];            // softmax aggregate
__device__ float g_pd[NSPLIT * B_ * HW_];  // partial denominators
__device__ float g_pn[NSPLIT * B_ * HW_];  // partial numerators

typedef unsigned int       u32;
typedef unsigned long long u64;

__device__ __forceinline__ u32 smem_u32(const void* p) {
    u32 a; asm("{ .reg .u64 t; cvta.to.shared.u64 t,%1; cvt.u32.u64 %0,t; }" : "=r"(a) : "l"(p));
    return a;
}
__device__ __forceinline__ void ldmx4(u32* r, u32 addr) {
    asm volatile("ldmatrix.sync.aligned.m8n8.x4.shared.b16 {%0,%1,%2,%3},[%4];"
                 : "=r"(r[0]), "=r"(r[1]), "=r"(r[2]), "=r"(r[3]) : "r"(addr));
}
__device__ __forceinline__ void mma_f16(float* c, const u32* a, u32 b0, u32 b1) {
    asm volatile("mma.sync.aligned.m16n8k16.row.col.f32.f16.f16.f32 "
                 "{%0,%1,%2,%3},{%4,%5,%6,%7},{%8,%9},{%0,%1,%2,%3};"
                 : "+f"(c[0]), "+f"(c[1]), "+f"(c[2]), "+f"(c[3])
                 : "r"(a[0]), "r"(a[1]), "r"(a[2]), "r"(a[3]), "r"(b0), "r"(b1));
}
#define CP16(sa, ga) asm volatile("cp.async.cg.shared.global [%0],[%1],16;" :: "r"(sa), "l"(ga))
#define CP_COMMIT()  asm volatile("cp.async.commit_group;" ::: "memory")
#define CP_WAIT(N)   asm volatile("cp.async.wait_group %0;" :: "n"(N) : "memory")

__device__ __forceinline__ u32 pack_h2(float a, float b) {
    __half2 t = __floats2half2_rn(a, b);
    return *(u32*)&t;
}

// exp(s) for s in [-1,1]: degree-8 Taylor (max rel err ~7.5e-6), FMA pipe only.
__device__ __forceinline__ float exp_poly(float s) {
    float e = fmaf(2.4801587e-5f, s, 1.9841270e-4f);
    e = fmaf(e, s, 1.3888889e-3f);
    e = fmaf(e, s, 8.3333333e-3f);
    e = fmaf(e, s, 4.1666667e-2f);
    e = fmaf(e, s, 0.16666667f);
    e = fmaf(e, s, 0.5f);
    e = fmaf(e, s, 1.0f);
    e = fmaf(e, s, 1.0f);
    return e;
}

// ---------------------------------------------------------------------------
// Setup: weights fp16 [m][k] (m 0..511: K then Q), biases fp32.
// ---------------------------------------------------------------------------
__global__ __launch_bounds__(256) void setup_kernel(
    const float* __restrict__ kw, const float* __restrict__ qw,
    const float* __restrict__ kb, const float* __restrict__ qb)
{
    int idx = blockIdx.x * 256 + threadIdx.x;      // 512x256 = 131072
    if (idx < 512) g_bias[idx] = (idx < 256) ? kb[idx] : qb[idx - 256];
    int m = idx >> 8, k = idx & 255;
    float w = (m < 256) ? kw[m * C_ + k] : qw[(m - 256) * C_ + k];
    g_wh[idx] = __float2half(w);
}

// ---------------------------------------------------------------------------
// Proj (fused): reads batch fp32, in-smem transpose -> fp16 A [n][c], value
// GEMV, then 64n x 512m x 256k fp16 GEMM (K cols 0..255, Q cols 256..511).
// 512 threads, 16 warps (2 wn x 8 wm), warp tile 32n x 64m.
// B (weights) triple-buffered in 32-col chunks; buf2 aliases dead fp32 stage.
// Mainloop ordering is WAIT -> sync -> issue (correct cp.async visibility).
// Epilogue: +bias, per-half row norms, normalized fp16 stores to g_kh/g_qh.
// ---------------------------------------------------------------------------
#define PA16_ST   528                       // A16 row stride bytes (64 rows)
#define PAS32_OFF 33792                     // fp32 staging, 256*65*4 = 66560 B
#define PAS32_F   8448                      // float index of staging
#define PB_TILE   40960                     // 512 rows x 80 B
#define PB01_OFF  100352                    // bufs 0,1
#define PSCR_F    45568                     // scratch float index (182272 B)
#define PROJ_SMEM 184832

__global__ __launch_bounds__(512, 1) void proj_kernel(
    const float* __restrict__ batch, const float* __restrict__ vw,
    const float* __restrict__ vb)
{
    extern __shared__ __align__(16) char sm[];
    float* smf = (float*)sm;
    const u32 smb = smem_u32(sm);
    const int tid = threadIdx.x, lane = tid & 31, wid = tid >> 5;
    const int wn = wid >> 3, wm = wid & 7;
    const int n0 = blockIdx.x * 64;
    const int b  = blockIdx.y;

    const char* srcB = (const char*)g_wh;

    // --- B prologue: chunks 0,1 into bufs 0,1 (cp.async; doesn't touch staging)
    {
        #pragma unroll
        for (int pc = 0; pc < 2; pc++) {
            const u32 dbase = smb + PB01_OFF + pc * PB_TILE;
            #pragma unroll
            for (int it = 0; it < 4; it++) {
                int s = tid + 512 * it;              // 2048 segs
                int r = s >> 2, q = s & 3;
                CP16(dbase + r * 80 + q * 16, srcB + (u64)r * 512 + pc * 64 + q * 16);
            }
            CP_COMMIT();
        }
    }

    // --- pass1: batch [c][n] fp32 -> staging smf[c*65 + n]
    #pragma unroll
    for (int it = 0; it < 8; it++) {
        int s = tid + 512 * it;                      // 4096 float4
        int c = s >> 4, nq = s & 15;
        float4 v4 = *(const float4*)(batch + ((size_t)(b * C_ + c)) * HW_ + n0 + 4 * nq);
        float* dst = smf + PAS32_F + c * 65 + 4 * nq;
        dst[0] = v4.x; dst[1] = v4.y; dst[2] = v4.z; dst[3] = v4.w;
    }
    __syncthreads();

    // --- pass2: staging -> A16 fp16 [n][c] (stride 528 B); 8192 half2 pairs
    #pragma unroll
    for (int it = 0; it < 16; it++) {
        int s = tid + 512 * it;                      // 64 rows x 128 pairs
        int cp = s & 127, n = s >> 7;
        float a = smf[PAS32_F + (2 * cp) * 65 + n];
        float d = smf[PAS32_F + (2 * cp + 1) * 65 + n];
        *(u32*)(sm + n * PA16_ST + 4 * cp) = pack_h2(a, d);
    }

    // --- value GEMV: warp w handles rows 4w..4w+3
    {
        const float vbv = __ldg(vb);
        #pragma unroll
        for (int rr = 0; rr < 4; rr++) {
            int n = 4 * wid + rr;
            float p = 0.f;
            #pragma unroll
            for (int j = 0; j < 8; j++) {
                int c = lane + 32 * j;
                p = fmaf(smf[PAS32_F + c * 65 + n], __ldg(vw + c), p);
            }
            #pragma unroll
            for (int o = 16; o; o >>= 1) p += __shfl_down_sync(0xFFFFFFFFu, p, o);
            if (lane == 0) g_v[b * HW_ + n0 + n] = p + vbv;
        }
    }
    __syncthreads();    // A16 ready; staging dead -> buf2 may alias it

    // --- ldmatrix lane bases
    const int qq = lane >> 3, rr = lane & 7;
    const u32 aBs = smb + (wn * 32 + (qq & 1) * 8 + rr) * PA16_ST + (qq >> 1) * 16;
    const u32 bLane = (wm * 64 + (qq & 1) * 8 + rr) * 80 + (qq >> 1) * 16;

    float C[2][8][4];
    #pragma unroll
    for (int i = 0; i < 2; i++)
        #pragma unroll
        for (int j = 0; j < 8; j++)
            #pragma unroll
            for (int k = 0; k < 4; k++) C[i][j][k] = 0.f;

    // --- mainloop: 8 chunks of 32 k-cols, depth-3 (buf2 aliased at PAS32_OFF)
    #pragma unroll
    for (int ch = 0; ch < 8; ch++) {
        if (ch < 7) { CP_WAIT(1); } else { CP_WAIT(0); }
        __syncthreads();
        if (ch < 6) {
            const int nb = (ch + 2) % 3;
            const u32 dbase = smb + (nb == 2 ? PAS32_OFF : PB01_OFF + nb * PB_TILE);
            #pragma unroll
            for (int it = 0; it < 4; it++) {
                int s = tid + 512 * it;
                int r = s >> 2, q = s & 3;
                CP16(dbase + r * 80 + q * 16, srcB + (u64)r * 512 + (ch + 2) * 64 + q * 16);
            }
            CP_COMMIT();
        }
        const int cb = ch % 3;
        const u32 B0 = smb + (cb == 2 ? PAS32_OFF : PB01_OFF + cb * PB_TILE) + bLane;
        const u32 A0 = aBs + ch * 64;
        #pragma unroll
        for (int ks = 0; ks < 2; ks++) {
            u32 ah[2][4], bh[4][4];
            #pragma unroll
            for (int ni = 0; ni < 2; ni++)
                ldmx4(ah[ni], A0 + ks * 32 + ni * 16 * PA16_ST);
            #pragma unroll
            for (int p = 0; p < 4; p++)
                ldmx4(bh[p], B0 + ks * 32 + p * 16 * 80);
            #pragma unroll
            for (int ni = 0; ni < 2; ni++)
                #pragma unroll
                for (int mj = 0; mj < 8; mj++) {
                    const int p = mj >> 1, w = mj & 1;
                    mma_f16(C[ni][mj], ah[ni], bh[p][w], bh[p][w + 2]);
                }
        }
    }
    __syncthreads();

    // --- epilogue: bias, per-half row norms, normalize, fp16 store ---
    float sl[2] = {0.f, 0.f}, sh[2] = {0.f, 0.f};
    #pragma unroll
    for (int ni = 0; ni < 2; ni++)
        #pragma unroll
        for (int mj = 0; mj < 8; mj++) {
            float2 bb = *(const float2*)&g_bias[wm * 64 + mj * 8 + (lane & 3) * 2];
            C[ni][mj][0] += bb.x; C[ni][mj][1] += bb.y;
            C[ni][mj][2] += bb.x; C[ni][mj][3] += bb.y;
            sl[ni] += C[ni][mj][0]*C[ni][mj][0] + C[ni][mj][1]*C[ni][mj][1];
            sh[ni] += C[ni][mj][2]*C[ni][mj][2] + C[ni][mj][3]*C[ni][mj][3];
        }
    #pragma unroll
    for (int ni = 0; ni < 2; ni++) {
        sl[ni] += __shfl_xor_sync(0xFFFFFFFFu, sl[ni], 1);
        sl[ni] += __shfl_xor_sync(0xFFFFFFFFu, sl[ni], 2);
        sh[ni] += __shfl_xor_sync(0xFFFFFFFFu, sh[ni], 1);
        sh[ni] += __shfl_xor_sync(0xFFFFFFFFu, sh[ni], 2);
    }
    float* normsm = smf + PSCR_F;        // [64 rows][8 wm]
    float* invsm  = normsm + 512;        // [64 rows][2 halves]
    if ((lane & 3) == 0) {
        int rbase = wn * 32 + (lane >> 2);
        #pragma unroll
        for (int ni = 0; ni < 2; ni++) {
            normsm[(rbase + ni * 16) * 8 + wm]     = sl[ni];
            normsm[(rbase + ni * 16 + 8) * 8 + wm] = sh[ni];
        }
    }
    __syncthreads();
    if (tid < 64) {
        float sK = 0.f, sQ = 0.f;
        #pragma unroll
        for (int w = 0; w < 4; w++) { sK += normsm[tid * 8 + w]; sQ += normsm[tid * 8 + 4 + w]; }
        invsm[tid * 2]     = 1.0f / fmaxf(sqrtf(sK), 1e-12f);
        invsm[tid * 2 + 1] = 1.0f / fmaxf(sqrtf(sQ), 1e-12f);
    }
    __syncthreads();

    __half* H = (wm < 4) ? g_kh : g_qh;
    const int half = (wm < 4) ? 0 : 1;
    const int cu = (wm & 3) * 32 + (lane & 3);     // u32 col base (x4 per mj)
    #pragma unroll
    for (int ni = 0; ni < 2; ni++) {
        int rl = wn * 32 + ni * 16 + (lane >> 2);
        float il = invsm[rl * 2 + half], ih = invsm[(rl + 8) * 2 + half];
        u32* d0 = (u32*)(H + (size_t)(b * HW_ + n0 + rl) * C_) + cu;
        u32* d1 = (u32*)(H + (size_t)(b * HW_ + n0 + rl + 8) * C_) + cu;
        #pragma unroll
        for (int mj = 0; mj < 8; mj++) {
            d0[mj * 4] = pack_h2(C[ni][mj][0] * il, C[ni][mj][1] * il);
            d1[mj * 4] = pack_h2(C[ni][mj][2] * ih, C[ni][mj][3] * ih);
        }
    }
}

// ---------------------------------------------------------------------------
// Attention: persistent B (q) tile [128m x 256c] in smem, 4 n-tiles of A (k)
// streamed through a depth-2 pipeline of 64-col chunks (16 iterations).
// grid (8 m, 16 b, 2 nz) = 256 blocks = single wave @ 2 CTA/SM.
// Pipeline: issue(it+1) -> compute(it) -> WAIT(0) -> sync.
// ---------------------------------------------------------------------------
#define ATB_ST   528
#define ATB_BYTES (128 * 528)          // 67584
#define ATA_TILE  (128 * 144)          // 18432
#define ATA_OFF   ATB_BYTES
#define ATTN_SMEM (ATB_BYTES + 2 * ATA_TILE)   // 104448

__global__ __launch_bounds__(256, 2) void attn_kernel()
{
    extern __shared__ __align__(16) char sm[];
    const u32 smb = smem_u32(sm);
    const int tid = threadIdx.x, lane = tid & 31, wid = tid >> 5;
    const int wn = wid >> 2, wm = wid & 3;
    const int m0 = blockIdx.x * 128, b = blockIdx.y, nz = blockIdx.z;
    const int nbase = nz * 512;

    const char* srcA = (const char*)(g_kh + (size_t)(b * HW_ + nbase) * C_);
    const char* srcB = (const char*)(g_qh + (size_t)(b * HW_ + m0) * C_);

    // persistent B tile: 128 rows x 512 B (stride 528), 4096 segs
    #pragma unroll
    for (int it = 0; it < 16; it++) {
        int s = tid + 256 * it;
        int r = s >> 5, q = s & 31;
        CP16(smb + r * ATB_ST + q * 16, srcB + (u64)r * 512 + q * 16);
    }
    CP_COMMIT();

    auto load_A = [&](int it, int buf) {       // it = nt*4 + ch
        const int nt = it >> 2, ch = it & 3;
        const u32 dbase = smb + ATA_OFF + buf * ATA_TILE;
        #pragma unroll
        for (int itr = 0; itr < 4; itr++) {    // 1024 segs
            int s = tid + 256 * itr;
            int r = s >> 3, q = s & 7;
            CP16(dbase + r * 144 + q * 16,
                 srcA + (u64)(nt * 128 + r) * 512 + ch * 128 + q * 16);
        }
        CP_COMMIT();
    };

    load_A(0, 0);
    CP_WAIT(0);
    __syncthreads();                           // B + A chunk0 visible

    const int qq = lane >> 3, rr = lane & 7;
    const u32 aB = smb + ATA_OFF + (wn * 64 + (qq & 1) * 8 + rr) * 144 + (qq >> 1) * 16;
    const u32 bB = smb + (wm * 32 + (qq & 1) * 8 + rr) * ATB_ST + (qq >> 1) * 16;

    float C[4][4][4];
    #pragma unroll
    for (int i = 0; i < 4; i++)
        #pragma unroll
        for (int j = 0; j < 4; j++)
            #pragma unroll
            for (int k = 0; k < 4; k++) C[i][j][k] = 0.f;

    float dsum[4][2] = {}, nsum[4][2] = {};

    #pragma unroll
    for (int it = 0; it < 16; it++) {
        if (it < 15) load_A(it + 1, (it + 1) & 1);   // overlaps compute(it)

        const int ch = it & 3, buf = it & 1;
        const u32 A0 = aB + buf * ATA_TILE;
        const u32 B0 = bB + ch * 128;
        #pragma unroll
        for (int ks = 0; ks < 4; ks++) {
            u32 ah[4][4], bh[2][4];
            #pragma unroll
            for (int ni = 0; ni < 4; ni++)
                ldmx4(ah[ni], A0 + ks * 32 + ni * 16 * 144);
            #pragma unroll
            for (int p = 0; p < 2; p++)
                ldmx4(bh[p], B0 + ks * 32 + p * 16 * ATB_ST);
            #pragma unroll
            for (int ni = 0; ni < 4; ni++)
                #pragma unroll
                for (int mj = 0; mj < 4; mj++) {
                    const int p = mj >> 1, w = mj & 1;
                    mma_f16(C[ni][mj], ah[ni], bh[p][w], bh[p][w + 2]);
                }
        }

        if (ch == 3) {                         // n-tile complete: exp + fold
            const int nt = it >> 2;
            #pragma unroll
            for (int ni = 0; ni < 4; ni++) {
                int nr = nbase + nt * 128 + wn * 64 + ni * 16 + (lane >> 2);
                float v0 = g_v[b * HW_ + nr];
                float v1 = g_v[b * HW_ + nr + 8];
                #pragma unroll
                for (int mj = 0; mj < 4; mj++) {
                    float e0 = exp_poly(C[ni][mj][0]);
                    float e1 = exp_poly(C[ni][mj][1]);
                    float e2 = exp_poly(C[ni][mj][2]);
                    float e3 = exp_poly(C[ni][mj][3]);
                    dsum[mj][0] += e0 + e2;
                    dsum[mj][1] += e1 + e3;
                    nsum[mj][0] = fmaf(v0, e0, fmaf(v1, e2, nsum[mj][0]));
                    nsum[mj][1] = fmaf(v0, e1, fmaf(v1, e3, nsum[mj][1]));
                    C[ni][mj][0] = 0.f; C[ni][mj][1] = 0.f;
                    C[ni][mj][2] = 0.f; C[ni][mj][3] = 0.f;
                }
            }
        }
        if (it < 15) { CP_WAIT(0); __syncthreads(); }   // publish chunk it+1
    }

    // cross-lane column reduce (over lane quads), then cross-wn via smem
    #pragma unroll
    for (int mj = 0; mj < 4; mj++)
        #pragma unroll
        for (int h = 0; h < 2; h++) {
            #pragma unroll
            for (int msk = 4; msk <= 16; msk <<= 1) {
                dsum[mj][h] += __shfl_xor_sync(0xFFFFFFFFu, dsum[mj][h], msk);
                nsum[mj][h] += __shfl_xor_sync(0xFFFFFFFFu, nsum[mj][h], msk);
            }
        }

    __syncthreads();                           // B tile dead; reuse as scratch
    float* redD = (float*)sm;
    float* redN = redD + 256;
    if (lane < 4) {
        #pragma unroll
        for (int mj = 0; mj < 4; mj++)
            #pragma unroll
            for (int h = 0; h < 2; h++) {
                int col = wm * 32 + mj * 8 + lane * 2 + h;
                redD[wn * 128 + col] = dsum[mj][h];
                redN[wn * 128 + col] = nsum[mj][h];
            }
    }
    __syncthreads();
    if (tid < 128) {
        g_pd[(size_t)(nz * B_ + b) * HW_ + m0 + tid] = redD[tid] + redD[128 + tid];
        g_pn[(size_t)(nz * B_ + b) * HW_ + m0 + tid] = redN[tid] + redN[128 + tid];
    }
}

// ---------------------------------------------------------------------------
// Combine partials: G = sum(num) / sum(den)
// ---------------------------------------------------------------------------
__global__ __launch_bounds__(256) void gfinal_kernel()
{
    int t = blockIdx.x * 256 + threadIdx.x;
    float D = 0.f, N = 0.f;
    #pragma unroll
    for (int z = 0; z < NSPLIT; z++) {
        D += g_pd[z * B_ * HW_ + t];
        N += g_pn[z * B_ * HW_ + t];
    }
    g_G[t] = N / D;
}

// ---------------------------------------------------------------------------
// Conv: out[b,c,i,j] = 3x3 box-sum of G[b,hw]*batch[b,c,hw]
// ---------------------------------------------------------------------------
__global__ __launch_bounds__(256) void conv_kernel(
    const float* __restrict__ batch, float* __restrict__ out)
{
    __shared__ float ys[HW_];
    const int c = blockIdx.x, b = blockIdx.y;
    const float* xb = batch + (b * C_ + c) * HW_;
    const float* Gb = g_G + b * HW_;
    {
        int i = threadIdx.x * 4;
        float4 x4 = *(const float4*)(xb + i);
        float4 g4 = *(const float4*)(Gb + i);
        ys[i]     = x4.x * g4.x;
        ys[i + 1] = x4.y * g4.y;
        ys[i + 2] = x4.z * g4.z;
        ys[i + 3] = x4.w * g4.w;
    }
    __syncthreads();
    float* ob = out + (b * C_ + c) * 900;
    for (int o = threadIdx.x; o < 900; o += 256) {
        int i = o / 30, j = o - i * 30;
        const float* y = ys + i * 32 + j;
        ob[o] = y[0] + y[1] + y[2] +
                y[32] + y[33] + y[34] +
                y[64] + y[65] + y[66];
    }
}

extern "C" void kernel_launch(void* const* d_in, const int* in_sizes, int n_in,
                              void* d_out, int out_size)
{
    const float* batch   = (const float*)d_in[0];
    const float* key_w   = (const float*)d_in[1];
    const float* key_b   = (const float*)d_in[2];
    const float* query_w = (const float*)d_in[3];
    const float* query_b = (const float*)d_in[4];
    const float* value_w = (const float*)d_in[5];
    const float* value_b = (const float*)d_in[6];
    // d_in[7] = local_indices (unused: collapses analytically to 3x3 box filter)

    cudaFuncSetAttribute(proj_kernel, cudaFuncAttributeMaxDynamicSharedMemorySize, PROJ_SMEM);
    cudaFuncSetAttribute(attn_kernel, cudaFuncAttributeMaxDynamicSharedMemorySize, ATTN_SMEM);

    setup_kernel<<<512, 256>>>(key_w, query_w, key_b, query_b);
    proj_kernel<<<dim3(16, 16), 512, PROJ_SMEM>>>(batch, value_w, value_b);
    attn_kernel<<<dim3(8, 16, NSPLIT), 256, ATTN_SMEM>>>();
    gfinal_kernel<<<64, 256>>>();
    conv_kernel<<<dim3(256, 16), 256>>>(batch, (float*)d_out);
}

// round 13
// speedup vs baseline: 1.0156x; 1.0156x over previous
#include <cuda_runtime.h>
#include <cuda_fp16.h>

#define B_  16
#define C_  256
#define HW_ 1024
#define NSPLIT 8

// ---- device scratch (no allocations allowed) ----
__device__ __half g_wh[512 * C_];        // weights [m][k]: m<256 K, else Q
__device__ __half g_kh[B_ * HW_ * C_];   // normalized keys    [b][n][c]
__device__ __half g_qh[B_ * HW_ * C_];   // normalized queries [b][m][c]
__device__ float g_bias[512];
__device__ float g_v[B_ * HW_];          // value scalars
__device__ float g_pd[B_ * HW_];         // denominators (atomic-accumulated)
__device__ float g_pn[B_ * HW_];         // numerators   (atomic-accumulated)

typedef unsigned int       u32;
typedef unsigned long long u64;

__device__ __forceinline__ u32 smem_u32(const void* p) {
    u32 a; asm("{ .reg .u64 t; cvta.to.shared.u64 t,%1; cvt.u32.u64 %0,t; }" : "=r"(a) : "l"(p));
    return a;
}
__device__ __forceinline__ void ldmx4(u32* r, u32 addr) {
    asm volatile("ldmatrix.sync.aligned.m8n8.x4.shared.b16 {%0,%1,%2,%3},[%4];"
                 : "=r"(r[0]), "=r"(r[1]), "=r"(r[2]), "=r"(r[3]) : "r"(addr));
}
__device__ __forceinline__ void mma_f16(float* c, const u32* a, u32 b0, u32 b1) {
    asm volatile("mma.sync.aligned.m16n8k16.row.col.f32.f16.f16.f32 "
                 "{%0,%1,%2,%3},{%4,%5,%6,%7},{%8,%9},{%0,%1,%2,%3};"
                 : "+f"(c[0]), "+f"(c[1]), "+f"(c[2]), "+f"(c[3])
                 : "r"(a[0]), "r"(a[1]), "r"(a[2]), "r"(a[3]), "r"(b0), "r"(b1));
}
#define CP16(sa, ga) asm volatile("cp.async.cg.shared.global [%0],[%1],16;" :: "r"(sa), "l"(ga))
#define CP_COMMIT()  asm volatile("cp.async.commit_group;" ::: "memory")
#define CP_WAIT(N)   asm volatile("cp.async.wait_group %0;" :: "n"(N) : "memory")

__device__ __forceinline__ u32 pack_h2(float a, float b) {
    __half2 t = __floats2half2_rn(a, b);
    return *(u32*)&t;
}

// exp(s) for s in [-1,1]: degree-8 Taylor (max rel err ~7.5e-6), FMA pipe only.
__device__ __forceinline__ float exp_poly(float s) {
    float e = fmaf(2.4801587e-5f, s, 1.9841270e-4f);
    e = fmaf(e, s, 1.3888889e-3f);
    e = fmaf(e, s, 8.3333333e-3f);
    e = fmaf(e, s, 4.1666667e-2f);
    e = fmaf(e, s, 0.16666667f);
    e = fmaf(e, s, 0.5f);
    e = fmaf(e, s, 1.0f);
    e = fmaf(e, s, 1.0f);
    return e;
}

// ---------------------------------------------------------------------------
// Setup: weights fp16 [m][k] (m 0..511: K then Q), biases fp32.
// Also zeroes the atomic accumulators (required every launch / graph replay).
// ---------------------------------------------------------------------------
__global__ __launch_bounds__(256) void setup_kernel(
    const float* __restrict__ kw, const float* __restrict__ qw,
    const float* __restrict__ kb, const float* __restrict__ qb)
{
    int idx = blockIdx.x * 256 + threadIdx.x;      // 512x256 = 131072
    if (idx < 512) g_bias[idx] = (idx < 256) ? kb[idx] : qb[idx - 256];
    if (idx < B_ * HW_) { g_pd[idx] = 0.f; g_pn[idx] = 0.f; }
    int m = idx >> 8, k = idx & 255;
    float w = (m < 256) ? kw[m * C_ + k] : qw[(m - 256) * C_ + k];
    g_wh[idx] = __float2half(w);
}

// ---------------------------------------------------------------------------
// Proj (fused): reads batch fp32, in-smem transpose -> fp16 A [n][c], value
// GEMV, then 64n x 512m x 256k fp16 GEMM (K cols 0..255, Q cols 256..511).
// 512 threads, 16 warps (2 wn x 8 wm), warp tile 32n x 64m.
// B (weights) triple-buffered in 32-col chunks; buf2 aliases dead fp32 stage.
// Mainloop ordering is WAIT -> sync -> issue (correct cp.async visibility).
// Epilogue: +bias, per-half row norms, normalized fp16 stores to g_kh/g_qh.
// ---------------------------------------------------------------------------
#define PA16_ST   528                       // A16 row stride bytes (64 rows)
#define PAS32_OFF 33792                     // fp32 staging, 256*65*4 = 66560 B
#define PAS32_F   8448                      // float index of staging
#define PB_TILE   40960                     // 512 rows x 80 B
#define PB01_OFF  100352                    // bufs 0,1
#define PSCR_F    45568                     // scratch float index (182272 B)
#define PROJ_SMEM 184832

__global__ __launch_bounds__(512, 1) void proj_kernel(
    const float* __restrict__ batch, const float* __restrict__ vw,
    const float* __restrict__ vb)
{
    extern __shared__ __align__(16) char sm[];
    float* smf = (float*)sm;
    const u32 smb = smem_u32(sm);
    const int tid = threadIdx.x, lane = tid & 31, wid = tid >> 5;
    const int wn = wid >> 3, wm = wid & 7;
    const int n0 = blockIdx.x * 64;
    const int b  = blockIdx.y;

    const char* srcB = (const char*)g_wh;

    // --- B prologue: chunks 0,1 into bufs 0,1 (cp.async; doesn't touch staging)
    {
        #pragma unroll
        for (int pc = 0; pc < 2; pc++) {
            const u32 dbase = smb + PB01_OFF + pc * PB_TILE;
            #pragma unroll
            for (int it = 0; it < 4; it++) {
                int s = tid + 512 * it;              // 2048 segs
                int r = s >> 2, q = s & 3;
                CP16(dbase + r * 80 + q * 16, srcB + (u64)r * 512 + pc * 64 + q * 16);
            }
            CP_COMMIT();
        }
    }

    // --- pass1: batch [c][n] fp32 -> staging smf[c*65 + n]
    #pragma unroll
    for (int it = 0; it < 8; it++) {
        int s = tid + 512 * it;                      // 4096 float4
        int c = s >> 4, nq = s & 15;
        float4 v4 = *(const float4*)(batch + ((size_t)(b * C_ + c)) * HW_ + n0 + 4 * nq);
        float* dst = smf + PAS32_F + c * 65 + 4 * nq;
        dst[0] = v4.x; dst[1] = v4.y; dst[2] = v4.z; dst[3] = v4.w;
    }
    __syncthreads();

    // --- pass2: staging -> A16 fp16 [n][c] (stride 528 B); 8192 half2 pairs
    #pragma unroll
    for (int it = 0; it < 16; it++) {
        int s = tid + 512 * it;                      // 64 rows x 128 pairs
        int cp = s & 127, n = s >> 7;
        float a = smf[PAS32_F + (2 * cp) * 65 + n];
        float d = smf[PAS32_F + (2 * cp + 1) * 65 + n];
        *(u32*)(sm + n * PA16_ST + 4 * cp) = pack_h2(a, d);
    }

    // --- value GEMV: warp w handles rows 4w..4w+3
    {
        const float vbv = __ldg(vb);
        #pragma unroll
        for (int rr = 0; rr < 4; rr++) {
            int n = 4 * wid + rr;
            float p = 0.f;
            #pragma unroll
            for (int j = 0; j < 8; j++) {
                int c = lane + 32 * j;
                p = fmaf(smf[PAS32_F + c * 65 + n], __ldg(vw + c), p);
            }
            #pragma unroll
            for (int o = 16; o; o >>= 1) p += __shfl_down_sync(0xFFFFFFFFu, p, o);
            if (lane == 0) g_v[b * HW_ + n0 + n] = p + vbv;
        }
    }
    __syncthreads();    // A16 ready; staging dead -> buf2 may alias it

    // --- ldmatrix lane bases
    const int qq = lane >> 3, rr = lane & 7;
    const u32 aBs = smb + (wn * 32 + (qq & 1) * 8 + rr) * PA16_ST + (qq >> 1) * 16;
    const u32 bLane = (wm * 64 + (qq & 1) * 8 + rr) * 80 + (qq >> 1) * 16;

    float C[2][8][4];
    #pragma unroll
    for (int i = 0; i < 2; i++)
        #pragma unroll
        for (int j = 0; j < 8; j++)
            #pragma unroll
            for (int k = 0; k < 4; k++) C[i][j][k] = 0.f;

    // --- mainloop: 8 chunks of 32 k-cols, depth-3 (buf2 aliased at PAS32_OFF)
    #pragma unroll
    for (int ch = 0; ch < 8; ch++) {
        if (ch < 7) { CP_WAIT(1); } else { CP_WAIT(0); }
        __syncthreads();
        if (ch < 6) {
            const int nb = (ch + 2) % 3;
            const u32 dbase = smb + (nb == 2 ? PAS32_OFF : PB01_OFF + nb * PB_TILE);
            #pragma unroll
            for (int it = 0; it < 4; it++) {
                int s = tid + 512 * it;
                int r = s >> 2, q = s & 3;
                CP16(dbase + r * 80 + q * 16, srcB + (u64)r * 512 + (ch + 2) * 64 + q * 16);
            }
            CP_COMMIT();
        }
        const int cb = ch % 3;
        const u32 B0 = smb + (cb == 2 ? PAS32_OFF : PB01_OFF + cb * PB_TILE) + bLane;
        const u32 A0 = aBs + ch * 64;
        #pragma unroll
        for (int ks = 0; ks < 2; ks++) {
            u32 ah[2][4], bh[4][4];
            #pragma unroll
            for (int ni = 0; ni < 2; ni++)
                ldmx4(ah[ni], A0 + ks * 32 + ni * 16 * PA16_ST);
            #pragma unroll
            for (int p = 0; p < 4; p++)
                ldmx4(bh[p], B0 + ks * 32 + p * 16 * 80);
            #pragma unroll
            for (int ni = 0; ni < 2; ni++)
                #pragma unroll
                for (int mj = 0; mj < 8; mj++) {
                    const int p = mj >> 1, w = mj & 1;
                    mma_f16(C[ni][mj], ah[ni], bh[p][w], bh[p][w + 2]);
                }
        }
    }
    __syncthreads();

    // --- epilogue: bias, per-half row norms, normalize, fp16 store ---
    float sl[2] = {0.f, 0.f}, sh[2] = {0.f, 0.f};
    #pragma unroll
    for (int ni = 0; ni < 2; ni++)
        #pragma unroll
        for (int mj = 0; mj < 8; mj++) {
            float2 bb = *(const float2*)&g_bias[wm * 64 + mj * 8 + (lane & 3) * 2];
            C[ni][mj][0] += bb.x; C[ni][mj][1] += bb.y;
            C[ni][mj][2] += bb.x; C[ni][mj][3] += bb.y;
            sl[ni] += C[ni][mj][0]*C[ni][mj][0] + C[ni][mj][1]*C[ni][mj][1];
            sh[ni] += C[ni][mj][2]*C[ni][mj][2] + C[ni][mj][3]*C[ni][mj][3];
        }
    #pragma unroll
    for (int ni = 0; ni < 2; ni++) {
        sl[ni] += __shfl_xor_sync(0xFFFFFFFFu, sl[ni], 1);
        sl[ni] += __shfl_xor_sync(0xFFFFFFFFu, sl[ni], 2);
        sh[ni] += __shfl_xor_sync(0xFFFFFFFFu, sh[ni], 1);
        sh[ni] += __shfl_xor_sync(0xFFFFFFFFu, sh[ni], 2);
    }
    float* normsm = smf + PSCR_F;        // [64 rows][8 wm]
    float* invsm  = normsm + 512;        // [64 rows][2 halves]
    if ((lane & 3) == 0) {
        int rbase = wn * 32 + (lane >> 2);
        #pragma unroll
        for (int ni = 0; ni < 2; ni++) {
            normsm[(rbase + ni * 16) * 8 + wm]     = sl[ni];
            normsm[(rbase + ni * 16 + 8) * 8 + wm] = sh[ni];
        }
    }
    __syncthreads();
    if (tid < 64) {
        float sK = 0.f, sQ = 0.f;
        #pragma unroll
        for (int w = 0; w < 4; w++) { sK += normsm[tid * 8 + w]; sQ += normsm[tid * 8 + 4 + w]; }
        invsm[tid * 2]     = 1.0f / fmaxf(sqrtf(sK), 1e-12f);
        invsm[tid * 2 + 1] = 1.0f / fmaxf(sqrtf(sQ), 1e-12f);
    }
    __syncthreads();

    __half* H = (wm < 4) ? g_kh : g_qh;
    const int half = (wm < 4) ? 0 : 1;
    const int cu = (wm & 3) * 32 + (lane & 3);     // u32 col base (x4 per mj)
    #pragma unroll
    for (int ni = 0; ni < 2; ni++) {
        int rl = wn * 32 + ni * 16 + (lane >> 2);
        float il = invsm[rl * 2 + half], ih = invsm[(rl + 8) * 2 + half];
        u32* d0 = (u32*)(H + (size_t)(b * HW_ + n0 + rl) * C_) + cu;
        u32* d1 = (u32*)(H + (size_t)(b * HW_ + n0 + rl + 8) * C_) + cu;
        #pragma unroll
        for (int mj = 0; mj < 8; mj++) {
            d0[mj * 4] = pack_h2(C[ni][mj][0] * il, C[ni][mj][1] * il);
            d1[mj * 4] = pack_h2(C[ni][mj][2] * ih, C[ni][mj][3] * ih);
        }
    }
}

// ---------------------------------------------------------------------------
// Attention via fp16 mma.sync: block = 128n x 128m x K=256, 4 chunks of 64
// k-cols, depth-3 pipeline (WAIT(1) -> sync -> issue(ch+2) -> compute(ch)).
// Epilogue: poly exp + column reduce -> atomicAdd into g_pd/g_pn.
// smem: 3 stages x (A[128x144] + B[128x144]) = 110592 B, 2 CTA/SM.
// ---------------------------------------------------------------------------
#define AT_TILE 18432            // 128 rows x 144 B
#define AT_STG  36864
#define ATTN_SMEM (3 * AT_STG)

__global__ __launch_bounds__(256, 2) void attn_kernel()
{
    extern __shared__ __align__(16) char sm[];
    const u32 smb = smem_u32(sm);
    const int tid = threadIdx.x, lane = tid & 31, wid = tid >> 5;
    const int wn = wid >> 2, wm = wid & 3;
    const int m0 = blockIdx.x * 128, b = blockIdx.y, nz = blockIdx.z;
    const int n0 = nz * 128;

    const char* srcA = (const char*)(g_kh + (size_t)(b * HW_ + n0) * C_);
    const char* srcB = (const char*)(g_qh + (size_t)(b * HW_ + m0) * C_);

    auto load_chunk = [&](int ch, int buf) {
        const u32 dbase = smb + buf * AT_STG;
        #pragma unroll
        for (int it = 0; it < 4; it++) {             // A tile: 1024 segs
            int s = tid + 256 * it;
            int r = s >> 3, q = s & 7;
            CP16(dbase + r * 144 + q * 16, srcA + (u64)r * 512 + ch * 128 + q * 16);
        }
        #pragma unroll
        for (int it = 0; it < 4; it++) {             // B tile
            int s = tid + 256 * it;
            int r = s >> 3, q = s & 7;
            CP16(dbase + AT_TILE + r * 144 + q * 16, srcB + (u64)r * 512 + ch * 128 + q * 16);
        }
        CP_COMMIT();
    };

    const int qq = lane >> 3, rr = lane & 7;
    const u32 aB = smb + (wn * 64 + (qq & 1) * 8 + rr) * 144 + (qq >> 1) * 16;
    const u32 bB = smb + AT_TILE + (wm * 32 + (qq & 1) * 8 + rr) * 144 + (qq >> 1) * 16;

    float C[4][4][4];
    #pragma unroll
    for (int i = 0; i < 4; i++)
        #pragma unroll
        for (int j = 0; j < 4; j++)
            #pragma unroll
            for (int k = 0; k < 4; k++) C[i][j][k] = 0.f;

    float v0[4], v1[4];
    #pragma unroll
    for (int ni = 0; ni < 4; ni++) {
        int nr = n0 + wn * 64 + ni * 16 + (lane >> 2);
        v0[ni] = g_v[b * HW_ + nr];
        v1[ni] = g_v[b * HW_ + nr + 8];
    }

    load_chunk(0, 0);
    load_chunk(1, 1);
    #pragma unroll
    for (int ch = 0; ch < 4; ch++) {
        if (ch < 3) { CP_WAIT(1); } else { CP_WAIT(0); }
        __syncthreads();                              // chunk ch published
        if (ch < 2) load_chunk(ch + 2, (ch + 2) % 3); // runs 2 chunks ahead

        const int buf = ch % 3;
        const u32 A0 = aB + buf * AT_STG;
        const u32 B0 = bB + buf * AT_STG;
        #pragma unroll
        for (int ks = 0; ks < 4; ks++) {
            u32 ah[4][4], bh[2][4];
            #pragma unroll
            for (int ni = 0; ni < 4; ni++)
                ldmx4(ah[ni], A0 + ks * 32 + ni * 16 * 144);
            #pragma unroll
            for (int p = 0; p < 2; p++)
                ldmx4(bh[p], B0 + ks * 32 + p * 16 * 144);
            #pragma unroll
            for (int ni = 0; ni < 4; ni++)
                #pragma unroll
                for (int mj = 0; mj < 4; mj++) {
                    const int p = mj >> 1, w = mj & 1;
                    mma_f16(C[ni][mj], ah[ni], bh[p][w], bh[p][w + 2]);
                }
        }
    }

    float dsum[4][2] = {}, nsum[4][2] = {};
    #pragma unroll
    for (int ni = 0; ni < 4; ni++)
        #pragma unroll
        for (int mj = 0; mj < 4; mj++) {
            float e0 = exp_poly(C[ni][mj][0]);
            float e1 = exp_poly(C[ni][mj][1]);
            float e2 = exp_poly(C[ni][mj][2]);
            float e3 = exp_poly(C[ni][mj][3]);
            dsum[mj][0] += e0 + e2;
            dsum[mj][1] += e1 + e3;
            nsum[mj][0] = fmaf(v0[ni], e0, fmaf(v1[ni], e2, nsum[mj][0]));
            nsum[mj][1] = fmaf(v0[ni], e1, fmaf(v1[ni], e3, nsum[mj][1]));
        }
    #pragma unroll
    for (int mj = 0; mj < 4; mj++)
        #pragma unroll
        for (int h = 0; h < 2; h++) {
            #pragma unroll
            for (int msk = 4; msk <= 16; msk <<= 1) {
                dsum[mj][h] += __shfl_xor_sync(0xFFFFFFFFu, dsum[mj][h], msk);
                nsum[mj][h] += __shfl_xor_sync(0xFFFFFFFFu, nsum[mj][h], msk);
            }
        }

    __syncthreads();
    float* redD = (float*)sm;
    float* redN = redD + 256;
    if (lane < 4) {
        #pragma unroll
        for (int mj = 0; mj < 4; mj++)
            #pragma unroll
            for (int h = 0; h < 2; h++) {
                int col = wm * 32 + mj * 8 + lane * 2 + h;
                redD[wn * 128 + col] = dsum[mj][h];
                redN[wn * 128 + col] = nsum[mj][h];
            }
    }
    __syncthreads();
    if (tid < 128) {
        atomicAdd(&g_pd[(size_t)b * HW_ + m0 + tid], redD[tid] + redD[128 + tid]);
        atomicAdd(&g_pn[(size_t)b * HW_ + m0 + tid], redN[tid] + redN[128 + tid]);
    }
}

// ---------------------------------------------------------------------------
// Conv (G fused): out[b,c,i,j] = 3x3 box-sum of (pn/pd)[b,hw]*batch[b,c,hw]
// ---------------------------------------------------------------------------
__global__ __launch_bounds__(256) void conv_kernel(
    const float* __restrict__ batch, float* __restrict__ out)
{
    __shared__ float ys[HW_];
    const int c = blockIdx.x, b = blockIdx.y;
    const float* xb = batch + (b * C_ + c) * HW_;
    {
        int i = threadIdx.x * 4;
        float4 x4 = *(const float4*)(xb + i);
        float4 d4 = *(const float4*)(g_pd + b * HW_ + i);
        float4 n4 = *(const float4*)(g_pn + b * HW_ + i);
        ys[i]     = (n4.x / d4.x) * x4.x;
        ys[i + 1] = (n4.y / d4.y) * x4.y;
        ys[i + 2] = (n4.z / d4.z) * x4.z;
        ys[i + 3] = (n4.w / d4.w) * x4.w;
    }
    __syncthreads();
    float* ob = out + (b * C_ + c) * 900;
    for (int o = threadIdx.x; o < 900; o += 256) {
        int i = o / 30, j = o - i * 30;
        const float* y = ys + i * 32 + j;
        ob[o] = y[0] + y[1] + y[2] +
                y[32] + y[33] + y[34] +
                y[64] + y[65] + y[66];
    }
}

extern "C" void kernel_launch(void* const* d_in, const int* in_sizes, int n_in,
                              void* d_out, int out_size)
{
    const float* batch   = (const float*)d_in[0];
    const float* key_w   = (const float*)d_in[1];
    const float* key_b   = (const float*)d_in[2];
    const float* query_w = (const float*)d_in[3];
    const float* query_b = (const float*)d_in[4];
    const float* value_w = (const float*)d_in[5];
    const float* value_b = (const float*)d_in[6];
    // d_in[7] = local_indices (unused: collapses analytically to 3x3 box filter)

    cudaFuncSetAttribute(proj_kernel, cudaFuncAttributeMaxDynamicSharedMemorySize, PROJ_SMEM);
    cudaFuncSetAttribute(attn_kernel, cudaFuncAttributeMaxDynamicSharedMemorySize, ATTN_SMEM);

    setup_kernel<<<512, 256>>>(key_w, query_w, key_b, query_b);
    proj_kernel<<<dim3(16, 16), 512, PROJ_SMEM>>>(batch, value_w, value_b);
    attn_kernel<<<dim3(8, 16, NSPLIT), 256, ATTN_SMEM>>>();
    conv_kernel<<<dim3(256, 16), 256>>>(batch, (float*)d_out);
}

// round 14
// speedup vs baseline: 1.0903x; 1.0735x over previous
#include <cuda_runtime.h>
#include <cuda_fp16.h>

#define B_  16
#define C_  256
#define HW_ 1024
#define NSPLIT 8

// ---- device scratch (no allocations allowed) ----
__device__ __half g_wh[512 * C_];        // weights [m][k]: m<256 K, else Q
__device__ __half g_kh[B_ * HW_ * C_];   // normalized keys    [b][n][c]
__device__ __half g_qh[B_ * HW_ * C_];   // normalized queries [b][m][c]
__device__ float g_bias[512];
__device__ float g_v[B_ * HW_];          // value scalars
__device__ float g_pd[B_ * HW_];         // denominators (atomic-accumulated)
__device__ float g_pn[B_ * HW_];         // numerators   (atomic-accumulated)

typedef unsigned int       u32;
typedef unsigned long long u64;

__device__ __forceinline__ u32 smem_u32(const void* p) {
    u32 a; asm("{ .reg .u64 t; cvta.to.shared.u64 t,%1; cvt.u32.u64 %0,t; }" : "=r"(a) : "l"(p));
    return a;
}
__device__ __forceinline__ void ldmx4(u32* r, u32 addr) {
    asm volatile("ldmatrix.sync.aligned.m8n8.x4.shared.b16 {%0,%1,%2,%3},[%4];"
                 : "=r"(r[0]), "=r"(r[1]), "=r"(r[2]), "=r"(r[3]) : "r"(addr));
}
__device__ __forceinline__ void mma_f16(float* c, const u32* a, u32 b0, u32 b1) {
    asm volatile("mma.sync.aligned.m16n8k16.row.col.f32.f16.f16.f32 "
                 "{%0,%1,%2,%3},{%4,%5,%6,%7},{%8,%9},{%0,%1,%2,%3};"
                 : "+f"(c[0]), "+f"(c[1]), "+f"(c[2]), "+f"(c[3])
                 : "r"(a[0]), "r"(a[1]), "r"(a[2]), "r"(a[3]), "r"(b0), "r"(b1));
}
#define CP16(sa, ga) asm volatile("cp.async.cg.shared.global [%0],[%1],16;" :: "r"(sa), "l"(ga))
#define CP_COMMIT()  asm volatile("cp.async.commit_group;" ::: "memory")
#define CP_WAIT(N)   asm volatile("cp.async.wait_group %0;" :: "n"(N) : "memory")

__device__ __forceinline__ u32 pack_h2(float a, float b) {
    __half2 t = __floats2half2_rn(a, b);
    return *(u32*)&t;
}

// exp(s) for s in [-1,1]: degree-8 Taylor (max rel err ~7.5e-6), FMA pipe only.
__device__ __forceinline__ float exp_poly(float s) {
    float e = fmaf(2.4801587e-5f, s, 1.9841270e-4f);
    e = fmaf(e, s, 1.3888889e-3f);
    e = fmaf(e, s, 8.3333333e-3f);
    e = fmaf(e, s, 4.1666667e-2f);
    e = fmaf(e, s, 0.16666667f);
    e = fmaf(e, s, 0.5f);
    e = fmaf(e, s, 1.0f);
    e = fmaf(e, s, 1.0f);
    return e;
}

// ---------------------------------------------------------------------------
// Setup: weights fp16 [m][k] (m 0..511: K then Q), biases fp32.
// Also zeroes the atomic accumulators (required every launch / graph replay).
// ---------------------------------------------------------------------------
__global__ __launch_bounds__(256) void setup_kernel(
    const float* __restrict__ kw, const float* __restrict__ qw,
    const float* __restrict__ kb, const float* __restrict__ qb)
{
    int idx = blockIdx.x * 256 + threadIdx.x;      // 512x256 = 131072
    if (idx < 512) g_bias[idx] = (idx < 256) ? kb[idx] : qb[idx - 256];
    if (idx < B_ * HW_) { g_pd[idx] = 0.f; g_pn[idx] = 0.f; }
    int m = idx >> 8, k = idx & 255;
    float w = (m < 256) ? kw[m * C_ + k] : qw[(m - 256) * C_ + k];
    g_wh[idx] = __float2half(w);
}

// ---------------------------------------------------------------------------
// Proj (fused): reads batch fp32, in-smem transpose -> fp16 A [n][c], value
// GEMV, then 64n x 512m x 256k fp16 GEMM (K cols 0..255, Q cols 256..511).
// 512 threads, 16 warps (2 wn x 8 wm), warp tile 32n x 64m.
// B (weights) triple-buffered in 32-col chunks; buf2 aliases dead fp32 stage.
// Mainloop ordering is WAIT -> sync -> issue (correct cp.async visibility).
// Epilogue: +bias, per-half row norms, normalized fp16 stores to g_kh/g_qh.
// ---------------------------------------------------------------------------
#define PA16_ST   528                       // A16 row stride bytes (64 rows)
#define PAS32_OFF 33792                     // fp32 staging, 256*65*4 = 66560 B
#define PAS32_F   8448                      // float index of staging
#define PB_TILE   40960                     // 512 rows x 80 B
#define PB01_OFF  100352                    // bufs 0,1
#define PSCR_F    45568                     // scratch float index (182272 B)
#define PROJ_SMEM 184832

__global__ __launch_bounds__(512, 1) void proj_kernel(
    const float* __restrict__ batch, const float* __restrict__ vw,
    const float* __restrict__ vb)
{
    extern __shared__ __align__(16) char sm[];
    float* smf = (float*)sm;
    const u32 smb = smem_u32(sm);
    const int tid = threadIdx.x, lane = tid & 31, wid = tid >> 5;
    const int wn = wid >> 3, wm = wid & 7;
    const int n0 = blockIdx.x * 64;
    const int b  = blockIdx.y;

    const char* srcB = (const char*)g_wh;

    // --- B prologue: chunks 0,1 into bufs 0,1 (cp.async; doesn't touch staging)
    {
        #pragma unroll
        for (int pc = 0; pc < 2; pc++) {
            const u32 dbase = smb + PB01_OFF + pc * PB_TILE;
            #pragma unroll
            for (int it = 0; it < 4; it++) {
                int s = tid + 512 * it;              // 2048 segs
                int r = s >> 2, q = s & 3;
                CP16(dbase + r * 80 + q * 16, srcB + (u64)r * 512 + pc * 64 + q * 16);
            }
            CP_COMMIT();
        }
    }

    // --- pass1: batch [c][n] fp32 -> staging smf[c*65 + n]
    #pragma unroll
    for (int it = 0; it < 8; it++) {
        int s = tid + 512 * it;                      // 4096 float4
        int c = s >> 4, nq = s & 15;
        float4 v4 = *(const float4*)(batch + ((size_t)(b * C_ + c)) * HW_ + n0 + 4 * nq);
        float* dst = smf + PAS32_F + c * 65 + 4 * nq;
        dst[0] = v4.x; dst[1] = v4.y; dst[2] = v4.z; dst[3] = v4.w;
    }
    __syncthreads();

    // --- pass2: staging -> A16 fp16 [n][c] (stride 528 B); 8192 half2 pairs
    #pragma unroll
    for (int it = 0; it < 16; it++) {
        int s = tid + 512 * it;                      // 64 rows x 128 pairs
        int cp = s & 127, n = s >> 7;
        float a = smf[PAS32_F + (2 * cp) * 65 + n];
        float d = smf[PAS32_F + (2 * cp + 1) * 65 + n];
        *(u32*)(sm + n * PA16_ST + 4 * cp) = pack_h2(a, d);
    }

    // --- value GEMV: warp w handles rows 4w..4w+3
    {
        const float vbv = __ldg(vb);
        #pragma unroll
        for (int rr = 0; rr < 4; rr++) {
            int n = 4 * wid + rr;
            float p = 0.f;
            #pragma unroll
            for (int j = 0; j < 8; j++) {
                int c = lane + 32 * j;
                p = fmaf(smf[PAS32_F + c * 65 + n], __ldg(vw + c), p);
            }
            #pragma unroll
            for (int o = 16; o; o >>= 1) p += __shfl_down_sync(0xFFFFFFFFu, p, o);
            if (lane == 0) g_v[b * HW_ + n0 + n] = p + vbv;
        }
    }
    __syncthreads();    // A16 ready; staging dead -> buf2 may alias it

    // --- ldmatrix lane bases
    const int qq = lane >> 3, rr = lane & 7;
    const u32 aBs = smb + (wn * 32 + (qq & 1) * 8 + rr) * PA16_ST + (qq >> 1) * 16;
    const u32 bLane = (wm * 64 + (qq & 1) * 8 + rr) * 80 + (qq >> 1) * 16;

    float C[2][8][4];
    #pragma unroll
    for (int i = 0; i < 2; i++)
        #pragma unroll
        for (int j = 0; j < 8; j++)
            #pragma unroll
            for (int k = 0; k < 4; k++) C[i][j][k] = 0.f;

    // --- mainloop: 8 chunks of 32 k-cols, depth-3 (buf2 aliased at PAS32_OFF)
    #pragma unroll
    for (int ch = 0; ch < 8; ch++) {
        if (ch < 7) { CP_WAIT(1); } else { CP_WAIT(0); }
        __syncthreads();
        if (ch < 6) {
            const int nb = (ch + 2) % 3;
            const u32 dbase = smb + (nb == 2 ? PAS32_OFF : PB01_OFF + nb * PB_TILE);
            #pragma unroll
            for (int it = 0; it < 4; it++) {
                int s = tid + 512 * it;
                int r = s >> 2, q = s & 3;
                CP16(dbase + r * 80 + q * 16, srcB + (u64)r * 512 + (ch + 2) * 64 + q * 16);
            }
            CP_COMMIT();
        }
        const int cb = ch % 3;
        const u32 B0 = smb + (cb == 2 ? PAS32_OFF : PB01_OFF + cb * PB_TILE) + bLane;
        const u32 A0 = aBs + ch * 64;
        #pragma unroll
        for (int ks = 0; ks < 2; ks++) {
            u32 ah[2][4], bh[4][4];
            #pragma unroll
            for (int ni = 0; ni < 2; ni++)
                ldmx4(ah[ni], A0 + ks * 32 + ni * 16 * PA16_ST);
            #pragma unroll
            for (int p = 0; p < 4; p++)
                ldmx4(bh[p], B0 + ks * 32 + p * 16 * 80);
            #pragma unroll
            for (int ni = 0; ni < 2; ni++)
                #pragma unroll
                for (int mj = 0; mj < 8; mj++) {
                    const int p = mj >> 1, w = mj & 1;
                    mma_f16(C[ni][mj], ah[ni], bh[p][w], bh[p][w + 2]);
                }
        }
    }
    __syncthreads();

    // --- epilogue: bias, per-half row norms, normalize, fp16 store ---
    float sl[2] = {0.f, 0.f}, sh[2] = {0.f, 0.f};
    #pragma unroll
    for (int ni = 0; ni < 2; ni++)
        #pragma unroll
        for (int mj = 0; mj < 8; mj++) {
            float2 bb = *(const float2*)&g_bias[wm * 64 + mj * 8 + (lane & 3) * 2];
            C[ni][mj][0] += bb.x; C[ni][mj][1] += bb.y;
            C[ni][mj][2] += bb.x; C[ni][mj][3] += bb.y;
            sl[ni] += C[ni][mj][0]*C[ni][mj][0] + C[ni][mj][1]*C[ni][mj][1];
            sh[ni] += C[ni][mj][2]*C[ni][mj][2] + C[ni][mj][3]*C[ni][mj][3];
        }
    #pragma unroll
    for (int ni = 0; ni < 2; ni++) {
        sl[ni] += __shfl_xor_sync(0xFFFFFFFFu, sl[ni], 1);
        sl[ni] += __shfl_xor_sync(0xFFFFFFFFu, sl[ni], 2);
        sh[ni] += __shfl_xor_sync(0xFFFFFFFFu, sh[ni], 1);
        sh[ni] += __shfl_xor_sync(0xFFFFFFFFu, sh[ni], 2);
    }
    float* normsm = smf + PSCR_F;        // [64 rows][8 wm]
    float* invsm  = normsm + 512;        // [64 rows][2 halves]
    if ((lane & 3) == 0) {
        int rbase = wn * 32 + (lane >> 2);
        #pragma unroll
        for (int ni = 0; ni < 2; ni++) {
            normsm[(rbase + ni * 16) * 8 + wm]     = sl[ni];
            normsm[(rbase + ni * 16 + 8) * 8 + wm] = sh[ni];
        }
    }
    __syncthreads();
    if (tid < 64) {
        float sK = 0.f, sQ = 0.f;
        #pragma unroll
        for (int w = 0; w < 4; w++) { sK += normsm[tid * 8 + w]; sQ += normsm[tid * 8 + 4 + w]; }
        invsm[tid * 2]     = 1.0f / fmaxf(sqrtf(sK), 1e-12f);
        invsm[tid * 2 + 1] = 1.0f / fmaxf(sqrtf(sQ), 1e-12f);
    }
    __syncthreads();

    __half* H = (wm < 4) ? g_kh : g_qh;
    const int half = (wm < 4) ? 0 : 1;
    const int cu = (wm & 3) * 32 + (lane & 3);     // u32 col base (x4 per mj)
    #pragma unroll
    for (int ni = 0; ni < 2; ni++) {
        int rl = wn * 32 + ni * 16 + (lane >> 2);
        float il = invsm[rl * 2 + half], ih = invsm[(rl + 8) * 2 + half];
        u32* d0 = (u32*)(H + (size_t)(b * HW_ + n0 + rl) * C_) + cu;
        u32* d1 = (u32*)(H + (size_t)(b * HW_ + n0 + rl + 8) * C_) + cu;
        #pragma unroll
        for (int mj = 0; mj < 8; mj++) {
            d0[mj * 4] = pack_h2(C[ni][mj][0] * il, C[ni][mj][1] * il);
            d1[mj * 4] = pack_h2(C[ni][mj][2] * ih, C[ni][mj][3] * ih);
        }
    }
}

// ---------------------------------------------------------------------------
// Attention via fp16 mma.sync: block = 128n x 128m x K=256, 4 chunks of 64
// k-cols, depth-3 pipeline (WAIT(1) -> sync -> issue(ch+2) -> compute(ch)).
// Epilogue: poly exp + column reduce -> atomicAdd into g_pd/g_pn.
// ---------------------------------------------------------------------------
#define AT_TILE 18432            // 128 rows x 144 B
#define AT_STG  36864
#define ATTN_SMEM (3 * AT_STG)

__global__ __launch_bounds__(256, 2) void attn_kernel()
{
    extern __shared__ __align__(16) char sm[];
    const u32 smb = smem_u32(sm);
    const int tid = threadIdx.x, lane = tid & 31, wid = tid >> 5;
    const int wn = wid >> 2, wm = wid & 3;
    const int m0 = blockIdx.x * 128, b = blockIdx.y, nz = blockIdx.z;
    const int n0 = nz * 128;

    const char* srcA = (const char*)(g_kh + (size_t)(b * HW_ + n0) * C_);
    const char* srcB = (const char*)(g_qh + (size_t)(b * HW_ + m0) * C_);

    auto load_chunk = [&](int ch, int buf) {
        const u32 dbase = smb + buf * AT_STG;
        #pragma unroll
        for (int it = 0; it < 4; it++) {             // A tile: 1024 segs
            int s = tid + 256 * it;
            int r = s >> 3, q = s & 7;
            CP16(dbase + r * 144 + q * 16, srcA + (u64)r * 512 + ch * 128 + q * 16);
        }
        #pragma unroll
        for (int it = 0; it < 4; it++) {             // B tile
            int s = tid + 256 * it;
            int r = s >> 3, q = s & 7;
            CP16(dbase + AT_TILE + r * 144 + q * 16, srcB + (u64)r * 512 + ch * 128 + q * 16);
        }
        CP_COMMIT();
    };

    const int qq = lane >> 3, rr = lane & 7;
    const u32 aB = smb + (wn * 64 + (qq & 1) * 8 + rr) * 144 + (qq >> 1) * 16;
    const u32 bB = smb + AT_TILE + (wm * 32 + (qq & 1) * 8 + rr) * 144 + (qq >> 1) * 16;

    float C[4][4][4];
    #pragma unroll
    for (int i = 0; i < 4; i++)
        #pragma unroll
        for (int j = 0; j < 4; j++)
            #pragma unroll
            for (int k = 0; k < 4; k++) C[i][j][k] = 0.f;

    float v0[4], v1[4];
    #pragma unroll
    for (int ni = 0; ni < 4; ni++) {
        int nr = n0 + wn * 64 + ni * 16 + (lane >> 2);
        v0[ni] = g_v[b * HW_ + nr];
        v1[ni] = g_v[b * HW_ + nr + 8];
    }

    load_chunk(0, 0);
    load_chunk(1, 1);
    #pragma unroll
    for (int ch = 0; ch < 4; ch++) {
        if (ch < 3) { CP_WAIT(1); } else { CP_WAIT(0); }
        __syncthreads();                              // chunk ch published
        if (ch < 2) load_chunk(ch + 2, (ch + 2) % 3); // runs 2 chunks ahead

        const int buf = ch % 3;
        const u32 A0 = aB + buf * AT_STG;
        const u32 B0 = bB + buf * AT_STG;
        #pragma unroll
        for (int ks = 0; ks < 4; ks++) {
            u32 ah[4][4], bh[2][4];
            #pragma unroll
            for (int ni = 0; ni < 4; ni++)
                ldmx4(ah[ni], A0 + ks * 32 + ni * 16 * 144);
            #pragma unroll
            for (int p = 0; p < 2; p++)
                ldmx4(bh[p], B0 + ks * 32 + p * 16 * 144);
            #pragma unroll
            for (int ni = 0; ni < 4; ni++)
                #pragma unroll
                for (int mj = 0; mj < 4; mj++) {
                    const int p = mj >> 1, w = mj & 1;
                    mma_f16(C[ni][mj], ah[ni], bh[p][w], bh[p][w + 2]);
                }
        }
    }

    float dsum[4][2] = {}, nsum[4][2] = {};
    #pragma unroll
    for (int ni = 0; ni < 4; ni++)
        #pragma unroll
        for (int mj = 0; mj < 4; mj++) {
            float e0 = exp_poly(C[ni][mj][0]);
            float e1 = exp_poly(C[ni][mj][1]);
            float e2 = exp_poly(C[ni][mj][2]);
            float e3 = exp_poly(C[ni][mj][3]);
            dsum[mj][0] += e0 + e2;
            dsum[mj][1] += e1 + e3;
            nsum[mj][0] = fmaf(v0[ni], e0, fmaf(v1[ni], e2, nsum[mj][0]));
            nsum[mj][1] = fmaf(v0[ni], e1, fmaf(v1[ni], e3, nsum[mj][1]));
        }
    #pragma unroll
    for (int mj = 0; mj < 4; mj++)
        #pragma unroll
        for (int h = 0; h < 2; h++) {
            #pragma unroll
            for (int msk = 4; msk <= 16; msk <<= 1) {
                dsum[mj][h] += __shfl_xor_sync(0xFFFFFFFFu, dsum[mj][h], msk);
                nsum[mj][h] += __shfl_xor_sync(0xFFFFFFFFu, nsum[mj][h], msk);
            }
        }

    __syncthreads();
    float* redD = (float*)sm;
    float* redN = redD + 256;
    if (lane < 4) {
        #pragma unroll
        for (int mj = 0; mj < 4; mj++)
            #pragma unroll
            for (int h = 0; h < 2; h++) {
                int col = wm * 32 + mj * 8 + lane * 2 + h;
                redD[wn * 128 + col] = dsum[mj][h];
                redN[wn * 128 + col] = nsum[mj][h];
            }
    }
    __syncthreads();
    if (tid < 128) {
        atomicAdd(&g_pd[(size_t)b * HW_ + m0 + tid], redD[tid] + redD[128 + tid]);
        atomicAdd(&g_pn[(size_t)b * HW_ + m0 + tid], redN[tid] + redN[128 + tid]);
    }
}

// ---------------------------------------------------------------------------
// Conv (register-sliding separable box filter, no smem):
// out[b,c,i,j] = sum_{di,dj<3} (pn/pd * x)[i+di][j+dj].
// Warp w owns output rows [4w, 4w+4) (warp 7: rows 28,29). Vertical 3-tap via
// a sliding register window; horizontal 3-tap via two shfl_down.
// ---------------------------------------------------------------------------
__global__ __launch_bounds__(256) void conv_kernel(
    const float* __restrict__ batch, float* __restrict__ out)
{
    const int c = blockIdx.x, b = blockIdx.y;
    const int lane = threadIdx.x & 31, w = threadIdx.x >> 5;
    const float* xb = batch + (size_t)(b * C_ + c) * HW_;
    const float* pn = g_pn + b * HW_;
    const float* pd = g_pd + b * HW_;

    const int ostart = w * 4;
    const int ocount = min(4, 30 - ostart);        // warp 7 -> 2

    auto ldrow = [&](int r) -> float {
        int idx = r * 32 + lane;
        return __fdividef(pn[idx], pd[idx]) * xb[idx];
    };

    float y0 = ldrow(ostart);
    float y1 = ldrow(ostart + 1);
    float* ob = out + (size_t)(b * C_ + c) * 900;
    #pragma unroll
    for (int k = 0; k < 4; k++) {
        if (k < ocount) {
            float y2 = ldrow(ostart + k + 2);
            float vs = y0 + y1 + y2;
            float s = vs + __shfl_down_sync(0xFFFFFFFFu, vs, 1)
                         + __shfl_down_sync(0xFFFFFFFFu, vs, 2);
            if (lane < 30) ob[(ostart + k) * 30 + lane] = s;
            y0 = y1; y1 = y2;
        }
    }
}

extern "C" void kernel_launch(void* const* d_in, const int* in_sizes, int n_in,
                              void* d_out, int out_size)
{
    const float* batch   = (const float*)d_in[0];
    const float* key_w   = (const float*)d_in[1];
    const float* key_b   = (const float*)d_in[2];
    const float* query_w = (const float*)d_in[3];
    const float* query_b = (const float*)d_in[4];
    const float* value_w = (const float*)d_in[5];
    const float* value_b = (const float*)d_in[6];
    // d_in[7] = local_indices (unused: collapses analytically to 3x3 box filter)

    cudaFuncSetAttribute(proj_kernel, cudaFuncAttributeMaxDynamicSharedMemorySize, PROJ_SMEM);
    cudaFuncSetAttribute(attn_kernel, cudaFuncAttributeMaxDynamicSharedMemorySize, ATTN_SMEM);

    setup_kernel<<<512, 256>>>(key_w, query_w, key_b, query_b);
    proj_kernel<<<dim3(16, 16), 512, PROJ_SMEM>>>(batch, value_w, value_b);
    attn_kernel<<<dim3(8, 16, NSPLIT), 256, ATTN_SMEM>>>();
    conv_kernel<<<dim3(256, 16), 256>>>(batch, (float*)d_out);
}

// round 15
// speedup vs baseline: 1.0936x; 1.0030x over previous
#include <cuda_runtime.h>
#include <cuda_fp16.h>

#define B_  16
#define C_  256
#define HW_ 1024
#define NSPLIT 8

// ---- device scratch (no allocations allowed) ----
__device__ __half g_wh[512 * C_];        // weights [m][k]: m<256 K, else Q
__device__ __half g_kh[B_ * HW_ * C_];   // normalized keys    [b][n][c]
__device__ __half g_qh[B_ * HW_ * C_];   // normalized queries [b][m][c]
__device__ float g_bias[512];
__device__ float g_v[B_ * HW_];          // value scalars
__device__ float g_pd[B_ * HW_];         // denominators (atomic-accumulated)
__device__ float g_pn[B_ * HW_];         // numerators   (atomic-accumulated)

typedef unsigned int       u32;
typedef unsigned long long u64;

__device__ __forceinline__ u32 smem_u32(const void* p) {
    u32 a; asm("{ .reg .u64 t; cvta.to.shared.u64 t,%1; cvt.u32.u64 %0,t; }" : "=r"(a) : "l"(p));
    return a;
}
__device__ __forceinline__ void ldmx4(u32* r, u32 addr) {
    asm volatile("ldmatrix.sync.aligned.m8n8.x4.shared.b16 {%0,%1,%2,%3},[%4];"
                 : "=r"(r[0]), "=r"(r[1]), "=r"(r[2]), "=r"(r[3]) : "r"(addr));
}
__device__ __forceinline__ void mma_f16(float* c, const u32* a, u32 b0, u32 b1) {
    asm volatile("mma.sync.aligned.m16n8k16.row.col.f32.f16.f16.f32 "
                 "{%0,%1,%2,%3},{%4,%5,%6,%7},{%8,%9},{%0,%1,%2,%3};"
                 : "+f"(c[0]), "+f"(c[1]), "+f"(c[2]), "+f"(c[3])
                 : "r"(a[0]), "r"(a[1]), "r"(a[2]), "r"(a[3]), "r"(b0), "r"(b1));
}
#define CP16(sa, ga) asm volatile("cp.async.cg.shared.global [%0],[%1],16;" :: "r"(sa), "l"(ga))
#define CP_COMMIT()  asm volatile("cp.async.commit_group;" ::: "memory")
#define CP_WAIT(N)   asm volatile("cp.async.wait_group %0;" :: "n"(N) : "memory")

__device__ __forceinline__ u32 pack_h2(float a, float b) {
    __half2 t = __floats2half2_rn(a, b);
    return *(u32*)&t;
}

// exp(s) for s in [-1,1]: degree-8 Taylor (max rel err ~7.5e-6), FMA pipe only.
__device__ __forceinline__ float exp_poly(float s) {
    float e = fmaf(2.4801587e-5f, s, 1.9841270e-4f);
    e = fmaf(e, s, 1.3888889e-3f);
    e = fmaf(e, s, 8.3333333e-3f);
    e = fmaf(e, s, 4.1666667e-2f);
    e = fmaf(e, s, 0.16666667f);
    e = fmaf(e, s, 0.5f);
    e = fmaf(e, s, 1.0f);
    e = fmaf(e, s, 1.0f);
    return e;
}

// ---------------------------------------------------------------------------
// Setup: weights fp16 [m][k] (m 0..511: K then Q), biases fp32.
// Also zeroes the atomic accumulators (required every launch / graph replay).
// ---------------------------------------------------------------------------
__global__ __launch_bounds__(256) void setup_kernel(
    const float* __restrict__ kw, const float* __restrict__ qw,
    const float* __restrict__ kb, const float* __restrict__ qb)
{
    int idx = blockIdx.x * 256 + threadIdx.x;      // 512x256 = 131072
    if (idx < 512) g_bias[idx] = (idx < 256) ? kb[idx] : qb[idx - 256];
    if (idx < B_ * HW_) { g_pd[idx] = 0.f; g_pn[idx] = 0.f; }
    int m = idx >> 8, k = idx & 255;
    float w = (m < 256) ? kw[m * C_ + k] : qw[(m - 256) * C_ + k];
    g_wh[idx] = __float2half(w);
}

// ---------------------------------------------------------------------------
// Proj (fused): reads batch fp32, in-smem transpose -> fp16 A [n][c], value
// GEMV, then 64n x 512m x 256k fp16 GEMM (K cols 0..255, Q cols 256..511).
// 512 threads, 16 warps (2 wn x 8 wm), warp tile 32n x 64m.
// B (weights) triple-buffered in 32-col chunks; buf2 aliases dead fp32 stage.
// Mainloop ordering is WAIT -> sync -> issue (correct cp.async visibility).
// Epilogue: +bias, per-half row norms, normalized fp16 stores to g_kh/g_qh.
// ---------------------------------------------------------------------------
#define PA16_ST   528                       // A16 row stride bytes (64 rows)
#define PAS32_OFF 33792                     // fp32 staging, 256*65*4 = 66560 B
#define PAS32_F   8448                      // float index of staging
#define PB_TILE   40960                     // 512 rows x 80 B
#define PB01_OFF  100352                    // bufs 0,1
#define PSCR_F    45568                     // scratch float index (182272 B)
#define PROJ_SMEM 184832

__global__ __launch_bounds__(512, 1) void proj_kernel(
    const float* __restrict__ batch, const float* __restrict__ vw,
    const float* __restrict__ vb)
{
    extern __shared__ __align__(16) char sm[];
    float* smf = (float*)sm;
    const u32 smb = smem_u32(sm);
    const int tid = threadIdx.x, lane = tid & 31, wid = tid >> 5;
    const int wn = wid >> 3, wm = wid & 7;
    const int n0 = blockIdx.x * 64;
    const int b  = blockIdx.y;

    const char* srcB = (const char*)g_wh;

    // --- B prologue: chunks 0,1 into bufs 0,1 (cp.async; doesn't touch staging)
    {
        #pragma unroll
        for (int pc = 0; pc < 2; pc++) {
            const u32 dbase = smb + PB01_OFF + pc * PB_TILE;
            #pragma unroll
            for (int it = 0; it < 4; it++) {
                int s = tid + 512 * it;              // 2048 segs
                int r = s >> 2, q = s & 3;
                CP16(dbase + r * 80 + q * 16, srcB + (u64)r * 512 + pc * 64 + q * 16);
            }
            CP_COMMIT();
        }
    }

    // --- pass1: batch [c][n] fp32 -> staging smf[c*65 + n]
    #pragma unroll
    for (int it = 0; it < 8; it++) {
        int s = tid + 512 * it;                      // 4096 float4
        int c = s >> 4, nq = s & 15;
        float4 v4 = *(const float4*)(batch + ((size_t)(b * C_ + c)) * HW_ + n0 + 4 * nq);
        float* dst = smf + PAS32_F + c * 65 + 4 * nq;
        dst[0] = v4.x; dst[1] = v4.y; dst[2] = v4.z; dst[3] = v4.w;
    }
    __syncthreads();

    // --- pass2: staging -> A16 fp16 [n][c] (stride 528 B); 8192 half2 pairs
    #pragma unroll
    for (int it = 0; it < 16; it++) {
        int s = tid + 512 * it;                      // 64 rows x 128 pairs
        int cp = s & 127, n = s >> 7;
        float a = smf[PAS32_F + (2 * cp) * 65 + n];
        float d = smf[PAS32_F + (2 * cp + 1) * 65 + n];
        *(u32*)(sm + n * PA16_ST + 4 * cp) = pack_h2(a, d);
    }

    // --- value GEMV: warp w handles rows 4w..4w+3
    {
        const float vbv = __ldg(vb);
        #pragma unroll
        for (int rr = 0; rr < 4; rr++) {
            int n = 4 * wid + rr;
            float p = 0.f;
            #pragma unroll
            for (int j = 0; j < 8; j++) {
                int c = lane + 32 * j;
                p = fmaf(smf[PAS32_F + c * 65 + n], __ldg(vw + c), p);
            }
            #pragma unroll
            for (int o = 16; o; o >>= 1) p += __shfl_down_sync(0xFFFFFFFFu, p, o);
            if (lane == 0) g_v[b * HW_ + n0 + n] = p + vbv;
        }
    }
    __syncthreads();    // A16 ready; staging dead -> buf2 may alias it

    // --- ldmatrix lane bases
    const int qq = lane >> 3, rr = lane & 7;
    const u32 aBs = smb + (wn * 32 + (qq & 1) * 8 + rr) * PA16_ST + (qq >> 1) * 16;
    const u32 bLane = (wm * 64 + (qq & 1) * 8 + rr) * 80 + (qq >> 1) * 16;

    float C[2][8][4];
    #pragma unroll
    for (int i = 0; i < 2; i++)
        #pragma unroll
        for (int j = 0; j < 8; j++)
            #pragma unroll
            for (int k = 0; k < 4; k++) C[i][j][k] = 0.f;

    // --- mainloop: 8 chunks of 32 k-cols, depth-3 (buf2 aliased at PAS32_OFF)
    #pragma unroll
    for (int ch = 0; ch < 8; ch++) {
        if (ch < 7) { CP_WAIT(1); } else { CP_WAIT(0); }
        __syncthreads();
        if (ch < 6) {
            const int nb = (ch + 2) % 3;
            const u32 dbase = smb + (nb == 2 ? PAS32_OFF : PB01_OFF + nb * PB_TILE);
            #pragma unroll
            for (int it = 0; it < 4; it++) {
                int s = tid + 512 * it;
                int r = s >> 2, q = s & 3;
                CP16(dbase + r * 80 + q * 16, srcB + (u64)r * 512 + (ch + 2) * 64 + q * 16);
            }
            CP_COMMIT();
        }
        const int cb = ch % 3;
        const u32 B0 = smb + (cb == 2 ? PAS32_OFF : PB01_OFF + cb * PB_TILE) + bLane;
        const u32 A0 = aBs + ch * 64;
        #pragma unroll
        for (int ks = 0; ks < 2; ks++) {
            u32 ah[2][4], bh[4][4];
            #pragma unroll
            for (int ni = 0; ni < 2; ni++)
                ldmx4(ah[ni], A0 + ks * 32 + ni * 16 * PA16_ST);
            #pragma unroll
            for (int p = 0; p < 4; p++)
                ldmx4(bh[p], B0 + ks * 32 + p * 16 * 80);
            #pragma unroll
            for (int ni = 0; ni < 2; ni++)
                #pragma unroll
                for (int mj = 0; mj < 8; mj++) {
                    const int p = mj >> 1, w = mj & 1;
                    mma_f16(C[ni][mj], ah[ni], bh[p][w], bh[p][w + 2]);
                }
        }
    }
    __syncthreads();

    // --- epilogue: bias, per-half row norms, normalize, fp16 store ---
    float sl[2] = {0.f, 0.f}, sh[2] = {0.f, 0.f};
    #pragma unroll
    for (int ni = 0; ni < 2; ni++)
        #pragma unroll
        for (int mj = 0; mj < 8; mj++) {
            float2 bb = *(const float2*)&g_bias[wm * 64 + mj * 8 + (lane & 3) * 2];
            C[ni][mj][0] += bb.x; C[ni][mj][1] += bb.y;
            C[ni][mj][2] += bb.x; C[ni][mj][3] += bb.y;
            sl[ni] += C[ni][mj][0]*C[ni][mj][0] + C[ni][mj][1]*C[ni][mj][1];
            sh[ni] += C[ni][mj][2]*C[ni][mj][2] + C[ni][mj][3]*C[ni][mj][3];
        }
    #pragma unroll
    for (int ni = 0; ni < 2; ni++) {
        sl[ni] += __shfl_xor_sync(0xFFFFFFFFu, sl[ni], 1);
        sl[ni] += __shfl_xor_sync(0xFFFFFFFFu, sl[ni], 2);
        sh[ni] += __shfl_xor_sync(0xFFFFFFFFu, sh[ni], 1);
        sh[ni] += __shfl_xor_sync(0xFFFFFFFFu, sh[ni], 2);
    }
    float* normsm = smf + PSCR_F;        // [64 rows][8 wm]
    float* invsm  = normsm + 512;        // [64 rows][2 halves]
    if ((lane & 3) == 0) {
        int rbase = wn * 32 + (lane >> 2);
        #pragma unroll
        for (int ni = 0; ni < 2; ni++) {
            normsm[(rbase + ni * 16) * 8 + wm]     = sl[ni];
            normsm[(rbase + ni * 16 + 8) * 8 + wm] = sh[ni];
        }
    }
    __syncthreads();
    if (tid < 64) {
        float sK = 0.f, sQ = 0.f;
        #pragma unroll
        for (int w = 0; w < 4; w++) { sK += normsm[tid * 8 + w]; sQ += normsm[tid * 8 + 4 + w]; }
        invsm[tid * 2]     = 1.0f / fmaxf(sqrtf(sK), 1e-12f);
        invsm[tid * 2 + 1] = 1.0f / fmaxf(sqrtf(sQ), 1e-12f);
    }
    __syncthreads();

    __half* H = (wm < 4) ? g_kh : g_qh;
    const int half = (wm < 4) ? 0 : 1;
    const int cu = (wm & 3) * 32 + (lane & 3);     // u32 col base (x4 per mj)
    #pragma unroll
    for (int ni = 0; ni < 2; ni++) {
        int rl = wn * 32 + ni * 16 + (lane >> 2);
        float il = invsm[rl * 2 + half], ih = invsm[(rl + 8) * 2 + half];
        u32* d0 = (u32*)(H + (size_t)(b * HW_ + n0 + rl) * C_) + cu;
        u32* d1 = (u32*)(H + (size_t)(b * HW_ + n0 + rl + 8) * C_) + cu;
        #pragma unroll
        for (int mj = 0; mj < 8; mj++) {
            d0[mj * 4] = pack_h2(C[ni][mj][0] * il, C[ni][mj][1] * il);
            d1[mj * 4] = pack_h2(C[ni][mj][2] * ih, C[ni][mj][3] * ih);
        }
    }
}

// ---------------------------------------------------------------------------
// Attention via fp16 mma.sync: block = 128n x 128m x K=256, 4 chunks of 64
// k-cols, depth-3 pipeline (WAIT(1) -> sync -> issue(ch+2) -> compute(ch)).
// Epilogue: poly exp + column reduce -> atomicAdd into g_pd/g_pn.
// ---------------------------------------------------------------------------
#define AT_TILE 18432            // 128 rows x 144 B
#define AT_STG  36864
#define ATTN_SMEM (3 * AT_STG)

__global__ __launch_bounds__(256, 2) void attn_kernel()
{
    extern __shared__ __align__(16) char sm[];
    const u32 smb = smem_u32(sm);
    const int tid = threadIdx.x, lane = tid & 31, wid = tid >> 5;
    const int wn = wid >> 2, wm = wid & 3;
    const int m0 = blockIdx.x * 128, b = blockIdx.y, nz = blockIdx.z;
    const int n0 = nz * 128;

    const char* srcA = (const char*)(g_kh + (size_t)(b * HW_ + n0) * C_);
    const char* srcB = (const char*)(g_qh + (size_t)(b * HW_ + m0) * C_);

    auto load_chunk = [&](int ch, int buf) {
        const u32 dbase = smb + buf * AT_STG;
        #pragma unroll
        for (int it = 0; it < 4; it++) {             // A tile: 1024 segs
            int s = tid + 256 * it;
            int r = s >> 3, q = s & 7;
            CP16(dbase + r * 144 + q * 16, srcA + (u64)r * 512 + ch * 128 + q * 16);
        }
        #pragma unroll
        for (int it = 0; it < 4; it++) {             // B tile
            int s = tid + 256 * it;
            int r = s >> 3, q = s & 7;
            CP16(dbase + AT_TILE + r * 144 + q * 16, srcB + (u64)r * 512 + ch * 128 + q * 16);
        }
        CP_COMMIT();
    };

    const int qq = lane >> 3, rr = lane & 7;
    const u32 aB = smb + (wn * 64 + (qq & 1) * 8 + rr) * 144 + (qq >> 1) * 16;
    const u32 bB = smb + AT_TILE + (wm * 32 + (qq & 1) * 8 + rr) * 144 + (qq >> 1) * 16;

    float C[4][4][4];
    #pragma unroll
    for (int i = 0; i < 4; i++)
        #pragma unroll
        for (int j = 0; j < 4; j++)
            #pragma unroll
            for (int k = 0; k < 4; k++) C[i][j][k] = 0.f;

    float v0[4], v1[4];
    #pragma unroll
    for (int ni = 0; ni < 4; ni++) {
        int nr = n0 + wn * 64 + ni * 16 + (lane >> 2);
        v0[ni] = g_v[b * HW_ + nr];
        v1[ni] = g_v[b * HW_ + nr + 8];
    }

    load_chunk(0, 0);
    load_chunk(1, 1);
    #pragma unroll
    for (int ch = 0; ch < 4; ch++) {
        if (ch < 3) { CP_WAIT(1); } else { CP_WAIT(0); }
        __syncthreads();                              // chunk ch published
        if (ch < 2) load_chunk(ch + 2, (ch + 2) % 3); // runs 2 chunks ahead

        const int buf = ch % 3;
        const u32 A0 = aB + buf * AT_STG;
        const u32 B0 = bB + buf * AT_STG;
        #pragma unroll
        for (int ks = 0; ks < 4; ks++) {
            u32 ah[4][4], bh[2][4];
            #pragma unroll
            for (int ni = 0; ni < 4; ni++)
                ldmx4(ah[ni], A0 + ks * 32 + ni * 16 * 144);
            #pragma unroll
            for (int p = 0; p < 2; p++)
                ldmx4(bh[p], B0 + ks * 32 + p * 16 * 144);
            #pragma unroll
            for (int ni = 0; ni < 4; ni++)
                #pragma unroll
                for (int mj = 0; mj < 4; mj++) {
                    const int p = mj >> 1, w = mj & 1;
                    mma_f16(C[ni][mj], ah[ni], bh[p][w], bh[p][w + 2]);
                }
        }
    }

    float dsum[4][2] = {}, nsum[4][2] = {};
    #pragma unroll
    for (int ni = 0; ni < 4; ni++)
        #pragma unroll
        for (int mj = 0; mj < 4; mj++) {
            float e0 = exp_poly(C[ni][mj][0]);
            float e1 = exp_poly(C[ni][mj][1]);
            float e2 = exp_poly(C[ni][mj][2]);
            float e3 = exp_poly(C[ni][mj][3]);
            dsum[mj][0] += e0 + e2;
            dsum[mj][1] += e1 + e3;
            nsum[mj][0] = fmaf(v0[ni], e0, fmaf(v1[ni], e2, nsum[mj][0]));
            nsum[mj][1] = fmaf(v0[ni], e1, fmaf(v1[ni], e3, nsum[mj][1]));
        }
    #pragma unroll
    for (int mj = 0; mj < 4; mj++)
        #pragma unroll
        for (int h = 0; h < 2; h++) {
            #pragma unroll
            for (int msk = 4; msk <= 16; msk <<= 1) {
                dsum[mj][h] += __shfl_xor_sync(0xFFFFFFFFu, dsum[mj][h], msk);
                nsum[mj][h] += __shfl_xor_sync(0xFFFFFFFFu, nsum[mj][h], msk);
            }
        }

    __syncthreads();
    float* redD = (float*)sm;
    float* redN = redD + 256;
    if (lane < 4) {
        #pragma unroll
        for (int mj = 0; mj < 4; mj++)
            #pragma unroll
            for (int h = 0; h < 2; h++) {
                int col = wm * 32 + mj * 8 + lane * 2 + h;
                redD[wn * 128 + col] = dsum[mj][h];
                redN[wn * 128 + col] = nsum[mj][h];
            }
    }
    __syncthreads();
    if (tid < 128) {
        atomicAdd(&g_pd[(size_t)b * HW_ + m0 + tid], redD[tid] + redD[128 + tid]);
        atomicAdd(&g_pn[(size_t)b * HW_ + m0 + tid], redN[tid] + redN[128 + tid]);
    }
}

// ---------------------------------------------------------------------------
// Conv (register-sliding separable box filter, no smem, MLP-maximized):
// out[b,c,i,j] = sum_{di,dj<3} (pn/pd * x)[i+di][j+dj].
// Warp w owns output rows [4w, 4w+4) (warp 7: rows 28,29). ALL window rows
// (pn, pd, x) are loaded up-front (18 independent LDGs -> MLP ~18), then the
// divides/sums/shfls run from registers.
// ---------------------------------------------------------------------------
__global__ __launch_bounds__(256) void conv_kernel(
    const float* __restrict__ batch, float* __restrict__ out)
{
    const int c = blockIdx.x, b = blockIdx.y;
    const int lane = threadIdx.x & 31, w = threadIdx.x >> 5;
    const float* xb = batch + (size_t)(b * C_ + c) * HW_;
    const float* pn = g_pn + b * HW_;
    const float* pd = g_pd + b * HW_;

    const int ostart = w * 4;
    const int nrows = (ostart == 28) ? 4 : 6;      // warp 7: rows 28..31 only
    const int ocount = (ostart == 28) ? 2 : 4;

    // batch-issue all loads first (independent -> high MLP)
    float xn[6], xd[6], xx[6];
    #pragma unroll
    for (int k = 0; k < 6; k++) {
        if (k < nrows) {
            int idx = (ostart + k) * 32 + lane;
            xn[k] = pn[idx];
            xd[k] = pd[idx];
            xx[k] = xb[idx];
        }
    }
    float y[6];
    #pragma unroll
    for (int k = 0; k < 6; k++)
        if (k < nrows) y[k] = __fdividef(xn[k], xd[k]) * xx[k];

    float* ob = out + (size_t)(b * C_ + c) * 900;
    #pragma unroll
    for (int k = 0; k < 4; k++) {
        if (k < ocount) {
            float vs = y[k] + y[k + 1] + y[k + 2];
            float s = vs + __shfl_down_sync(0xFFFFFFFFu, vs, 1)
                         + __shfl_down_sync(0xFFFFFFFFu, vs, 2);
            if (lane < 30) ob[(ostart + k) * 30 + lane] = s;
        }
    }
}

extern "C" void kernel_launch(void* const* d_in, const int* in_sizes, int n_in,
                              void* d_out, int out_size)
{
    const float* batch   = (const float*)d_in[0];
    const float* key_w   = (const float*)d_in[1];
    const float* key_b   = (const float*)d_in[2];
    const float* query_w = (const float*)d_in[3];
    const float* query_b = (const float*)d_in[4];
    const float* value_w = (const float*)d_in[5];
    const float* value_b = (const float*)d_in[6];
    // d_in[7] = local_indices (unused: collapses analytically to 3x3 box filter)

    cudaFuncSetAttribute(proj_kernel, cudaFuncAttributeMaxDynamicSharedMemorySize, PROJ_SMEM);
    cudaFuncSetAttribute(attn_kernel, cudaFuncAttributeMaxDynamicSharedMemorySize, ATTN_SMEM);

    setup_kernel<<<512, 256>>>(key_w, query_w, key_b, query_b);
    proj_kernel<<<dim3(16, 16), 512, PROJ_SMEM>>>(batch, value_w, value_b);
    attn_kernel<<<dim3(8, 16, NSPLIT), 256, ATTN_SMEM>>>();
    conv_kernel<<<dim3(256, 16), 256>>>(batch, (float*)d_out);
}

// round 16
// speedup vs baseline: 1.1246x; 1.0284x over previous
#include <cuda_runtime.h>
#include <cuda_fp16.h>

#define B_  16
#define C_  256
#define HW_ 1024
#define NSPLIT 8

// ---- device scratch (no allocations allowed) ----
__device__ __half g_wh[512 * C_];        // weights [m][k]: m<256 K, else Q
__device__ __half g_kh[B_ * HW_ * C_];   // normalized keys    [b][n][c]
__device__ __half g_qh[B_ * HW_ * C_];   // normalized queries [b][m][c]
__device__ float g_bias[512];
__device__ float g_v[B_ * HW_];          // value scalars
__device__ float g_pd[B_ * HW_];         // denominators (atomic-accumulated)
__device__ float g_pn[B_ * HW_];         // numerators   (atomic-accumulated)

typedef unsigned int       u32;
typedef unsigned long long u64;

__device__ __forceinline__ u32 smem_u32(const void* p) {
    u32 a; asm("{ .reg .u64 t; cvta.to.shared.u64 t,%1; cvt.u32.u64 %0,t; }" : "=r"(a) : "l"(p));
    return a;
}
__device__ __forceinline__ void ldmx4(u32* r, u32 addr) {
    asm volatile("ldmatrix.sync.aligned.m8n8.x4.shared.b16 {%0,%1,%2,%3},[%4];"
                 : "=r"(r[0]), "=r"(r[1]), "=r"(r[2]), "=r"(r[3]) : "r"(addr));
}
__device__ __forceinline__ void mma_f16(float* c, const u32* a, u32 b0, u32 b1) {
    asm volatile("mma.sync.aligned.m16n8k16.row.col.f32.f16.f16.f32 "
                 "{%0,%1,%2,%3},{%4,%5,%6,%7},{%8,%9},{%0,%1,%2,%3};"
                 : "+f"(c[0]), "+f"(c[1]), "+f"(c[2]), "+f"(c[3])
                 : "r"(a[0]), "r"(a[1]), "r"(a[2]), "r"(a[3]), "r"(b0), "r"(b1));
}
#define CP16(sa, ga) asm volatile("cp.async.cg.shared.global [%0],[%1],16;" :: "r"(sa), "l"(ga))
#define CP_COMMIT()  asm volatile("cp.async.commit_group;" ::: "memory")
#define CP_WAIT(N)   asm volatile("cp.async.wait_group %0;" :: "n"(N) : "memory")

__device__ __forceinline__ u32 pack_h2(float a, float b) {
    __half2 t = __floats2half2_rn(a, b);
    return *(u32*)&t;
}

// exp(s) for s in [-1,1]: degree-8 Taylor (max rel err ~7.5e-6), FMA pipe only.
__device__ __forceinline__ float exp_poly(float s) {
    float e = fmaf(2.4801587e-5f, s, 1.9841270e-4f);
    e = fmaf(e, s, 1.3888889e-3f);
    e = fmaf(e, s, 8.3333333e-3f);
    e = fmaf(e, s, 4.1666667e-2f);
    e = fmaf(e, s, 0.16666667f);
    e = fmaf(e, s, 0.5f);
    e = fmaf(e, s, 1.0f);
    e = fmaf(e, s, 1.0f);
    return e;
}

// ---------------------------------------------------------------------------
// Setup: weights fp16 [m][k] (m 0..511: K then Q), biases fp32.
// Also zeroes the atomic accumulators (required every launch / graph replay).
// ---------------------------------------------------------------------------
__global__ __launch_bounds__(256) void setup_kernel(
    const float* __restrict__ kw, const float* __restrict__ qw,
    const float* __restrict__ kb, const float* __restrict__ qb)
{
    int idx = blockIdx.x * 256 + threadIdx.x;      // 512x256 = 131072
    if (idx < 512) g_bias[idx] = (idx < 256) ? kb[idx] : qb[idx - 256];
    if (idx < B_ * HW_) { g_pd[idx] = 0.f; g_pn[idx] = 0.f; }
    int m = idx >> 8, k = idx & 255;
    float w = (m < 256) ? kw[m * C_ + k] : qw[(m - 256) * C_ + k];
    g_wh[idx] = __float2half(w);
}

// ---------------------------------------------------------------------------
// Proj (fused): reads batch fp32, in-smem transpose -> fp16 A [n][c], value
// GEMV, then 64n x 512m x 256k fp16 GEMM (K cols 0..255, Q cols 256..511).
// 512 threads, 16 warps (2 wn x 8 wm), warp tile 32n x 64m.
// B (weights) triple-buffered in 32-col chunks; buf2 aliases dead fp32 stage.
// Mainloop ordering is WAIT -> sync -> issue (correct cp.async visibility).
// Epilogue: +bias, per-half row norms, normalized fp16 stores to g_kh/g_qh.
// ---------------------------------------------------------------------------
#define PA16_ST   528                       // A16 row stride bytes (64 rows)
#define PAS32_OFF 33792                     // fp32 staging, 256*65*4 = 66560 B
#define PAS32_F   8448                      // float index of staging
#define PB_TILE   40960                     // 512 rows x 80 B
#define PB01_OFF  100352                    // bufs 0,1
#define PSCR_F    45568                     // scratch float index (182272 B)
#define PROJ_SMEM 184832

__global__ __launch_bounds__(512, 1) void proj_kernel(
    const float* __restrict__ batch, const float* __restrict__ vw,
    const float* __restrict__ vb)
{
    extern __shared__ __align__(16) char sm[];
    float* smf = (float*)sm;
    const u32 smb = smem_u32(sm);
    const int tid = threadIdx.x, lane = tid & 31, wid = tid >> 5;
    const int wn = wid >> 3, wm = wid & 7;
    const int n0 = blockIdx.x * 64;
    const int b  = blockIdx.y;

    const char* srcB = (const char*)g_wh;

    // --- B prologue: chunks 0,1 into bufs 0,1 (cp.async; doesn't touch staging)
    {
        #pragma unroll
        for (int pc = 0; pc < 2; pc++) {
            const u32 dbase = smb + PB01_OFF + pc * PB_TILE;
            #pragma unroll
            for (int it = 0; it < 4; it++) {
                int s = tid + 512 * it;              // 2048 segs
                int r = s >> 2, q = s & 3;
                CP16(dbase + r * 80 + q * 16, srcB + (u64)r * 512 + pc * 64 + q * 16);
            }
            CP_COMMIT();
        }
    }

    // --- pass1: batch [c][n] fp32 -> staging smf[c*65 + n]
    #pragma unroll
    for (int it = 0; it < 8; it++) {
        int s = tid + 512 * it;                      // 4096 float4
        int c = s >> 4, nq = s & 15;
        float4 v4 = *(const float4*)(batch + ((size_t)(b * C_ + c)) * HW_ + n0 + 4 * nq);
        float* dst = smf + PAS32_F + c * 65 + 4 * nq;
        dst[0] = v4.x; dst[1] = v4.y; dst[2] = v4.z; dst[3] = v4.w;
    }
    __syncthreads();

    // --- pass2: staging -> A16 fp16 [n][c] (stride 528 B); 8192 half2 pairs
    #pragma unroll
    for (int it = 0; it < 16; it++) {
        int s = tid + 512 * it;                      // 64 rows x 128 pairs
        int cp = s & 127, n = s >> 7;
        float a = smf[PAS32_F + (2 * cp) * 65 + n];
        float d = smf[PAS32_F + (2 * cp + 1) * 65 + n];
        *(u32*)(sm + n * PA16_ST + 4 * cp) = pack_h2(a, d);
    }

    // --- value GEMV: warp w handles rows 4w..4w+3
    {
        const float vbv = __ldg(vb);
        #pragma unroll
        for (int rr = 0; rr < 4; rr++) {
            int n = 4 * wid + rr;
            float p = 0.f;
            #pragma unroll
            for (int j = 0; j < 8; j++) {
                int c = lane + 32 * j;
                p = fmaf(smf[PAS32_F + c * 65 + n], __ldg(vw + c), p);
            }
            #pragma unroll
            for (int o = 16; o; o >>= 1) p += __shfl_down_sync(0xFFFFFFFFu, p, o);
            if (lane == 0) g_v[b * HW_ + n0 + n] = p + vbv;
        }
    }
    __syncthreads();    // A16 ready; staging dead -> buf2 may alias it

    // --- ldmatrix lane bases
    const int qq = lane >> 3, rr = lane & 7;
    const u32 aBs = smb + (wn * 32 + (qq & 1) * 8 + rr) * PA16_ST + (qq >> 1) * 16;
    const u32 bLane = (wm * 64 + (qq & 1) * 8 + rr) * 80 + (qq >> 1) * 16;

    float C[2][8][4];
    #pragma unroll
    for (int i = 0; i < 2; i++)
        #pragma unroll
        for (int j = 0; j < 8; j++)
            #pragma unroll
            for (int k = 0; k < 4; k++) C[i][j][k] = 0.f;

    // --- mainloop: 8 chunks of 32 k-cols, depth-3 (buf2 aliased at PAS32_OFF)
    #pragma unroll
    for (int ch = 0; ch < 8; ch++) {
        if (ch < 7) { CP_WAIT(1); } else { CP_WAIT(0); }
        __syncthreads();
        if (ch < 6) {
            const int nb = (ch + 2) % 3;
            const u32 dbase = smb + (nb == 2 ? PAS32_OFF : PB01_OFF + nb * PB_TILE);
            #pragma unroll
            for (int it = 0; it < 4; it++) {
                int s = tid + 512 * it;
                int r = s >> 2, q = s & 3;
                CP16(dbase + r * 80 + q * 16, srcB + (u64)r * 512 + (ch + 2) * 64 + q * 16);
            }
            CP_COMMIT();
        }
        const int cb = ch % 3;
        const u32 B0 = smb + (cb == 2 ? PAS32_OFF : PB01_OFF + cb * PB_TILE) + bLane;
        const u32 A0 = aBs + ch * 64;
        #pragma unroll
        for (int ks = 0; ks < 2; ks++) {
            u32 ah[2][4], bh[4][4];
            #pragma unroll
            for (int ni = 0; ni < 2; ni++)
                ldmx4(ah[ni], A0 + ks * 32 + ni * 16 * PA16_ST);
            #pragma unroll
            for (int p = 0; p < 4; p++)
                ldmx4(bh[p], B0 + ks * 32 + p * 16 * 80);
            #pragma unroll
            for (int ni = 0; ni < 2; ni++)
                #pragma unroll
                for (int mj = 0; mj < 8; mj++) {
                    const int p = mj >> 1, w = mj & 1;
                    mma_f16(C[ni][mj], ah[ni], bh[p][w], bh[p][w + 2]);
                }
        }
    }
    __syncthreads();

    // --- epilogue: bias, per-half row norms, normalize, fp16 store ---
    float sl[2] = {0.f, 0.f}, sh[2] = {0.f, 0.f};
    #pragma unroll
    for (int ni = 0; ni < 2; ni++)
        #pragma unroll
        for (int mj = 0; mj < 8; mj++) {
            float2 bb = *(const float2*)&g_bias[wm * 64 + mj * 8 + (lane & 3) * 2];
            C[ni][mj][0] += bb.x; C[ni][mj][1] += bb.y;
            C[ni][mj][2] += bb.x; C[ni][mj][3] += bb.y;
            sl[ni] += C[ni][mj][0]*C[ni][mj][0] + C[ni][mj][1]*C[ni][mj][1];
            sh[ni] += C[ni][mj][2]*C[ni][mj][2] + C[ni][mj][3]*C[ni][mj][3];
        }
    #pragma unroll
    for (int ni = 0; ni < 2; ni++) {
        sl[ni] += __shfl_xor_sync(0xFFFFFFFFu, sl[ni], 1);
        sl[ni] += __shfl_xor_sync(0xFFFFFFFFu, sl[ni], 2);
        sh[ni] += __shfl_xor_sync(0xFFFFFFFFu, sh[ni], 1);
        sh[ni] += __shfl_xor_sync(0xFFFFFFFFu, sh[ni], 2);
    }
    float* normsm = smf + PSCR_F;        // [64 rows][8 wm]
    float* invsm  = normsm + 512;        // [64 rows][2 halves]
    if ((lane & 3) == 0) {
        int rbase = wn * 32 + (lane >> 2);
        #pragma unroll
        for (int ni = 0; ni < 2; ni++) {
            normsm[(rbase + ni * 16) * 8 + wm]     = sl[ni];
            normsm[(rbase + ni * 16 + 8) * 8 + wm] = sh[ni];
        }
    }
    __syncthreads();
    if (tid < 64) {
        float sK = 0.f, sQ = 0.f;
        #pragma unroll
        for (int w = 0; w < 4; w++) { sK += normsm[tid * 8 + w]; sQ += normsm[tid * 8 + 4 + w]; }
        invsm[tid * 2]     = 1.0f / fmaxf(sqrtf(sK), 1e-12f);
        invsm[tid * 2 + 1] = 1.0f / fmaxf(sqrtf(sQ), 1e-12f);
    }
    __syncthreads();

    __half* H = (wm < 4) ? g_kh : g_qh;
    const int half = (wm < 4) ? 0 : 1;
    const int cu = (wm & 3) * 32 + (lane & 3);     // u32 col base (x4 per mj)
    #pragma unroll
    for (int ni = 0; ni < 2; ni++) {
        int rl = wn * 32 + ni * 16 + (lane >> 2);
        float il = invsm[rl * 2 + half], ih = invsm[(rl + 8) * 2 + half];
        u32* d0 = (u32*)(H + (size_t)(b * HW_ + n0 + rl) * C_) + cu;
        u32* d1 = (u32*)(H + (size_t)(b * HW_ + n0 + rl + 8) * C_) + cu;
        #pragma unroll
        for (int mj = 0; mj < 8; mj++) {
            d0[mj * 4] = pack_h2(C[ni][mj][0] * il, C[ni][mj][1] * il);
            d1[mj * 4] = pack_h2(C[ni][mj][2] * ih, C[ni][mj][3] * ih);
        }
    }
}

// ---------------------------------------------------------------------------
// Attention via fp16 mma.sync: block = 128n x 128m x K=256, 4 chunks of 64
// k-cols, depth-3 pipeline (WAIT(1) -> sync -> issue(ch+2) -> compute(ch)).
// Epilogue: poly exp + column reduce -> atomicAdd into g_pd/g_pn.
// ---------------------------------------------------------------------------
#define AT_TILE 18432            // 128 rows x 144 B
#define AT_STG  36864
#define ATTN_SMEM (3 * AT_STG)

__global__ __launch_bounds__(256, 2) void attn_kernel()
{
    extern __shared__ __align__(16) char sm[];
    const u32 smb = smem_u32(sm);
    const int tid = threadIdx.x, lane = tid & 31, wid = tid >> 5;
    const int wn = wid >> 2, wm = wid & 3;
    const int m0 = blockIdx.x * 128, b = blockIdx.y, nz = blockIdx.z;
    const int n0 = nz * 128;

    const char* srcA = (const char*)(g_kh + (size_t)(b * HW_ + n0) * C_);
    const char* srcB = (const char*)(g_qh + (size_t)(b * HW_ + m0) * C_);

    auto load_chunk = [&](int ch, int buf) {
        const u32 dbase = smb + buf * AT_STG;
        #pragma unroll
        for (int it = 0; it < 4; it++) {             // A tile: 1024 segs
            int s = tid + 256 * it;
            int r = s >> 3, q = s & 7;
            CP16(dbase + r * 144 + q * 16, srcA + (u64)r * 512 + ch * 128 + q * 16);
        }
        #pragma unroll
        for (int it = 0; it < 4; it++) {             // B tile
            int s = tid + 256 * it;
            int r = s >> 3, q = s & 7;
            CP16(dbase + AT_TILE + r * 144 + q * 16, srcB + (u64)r * 512 + ch * 128 + q * 16);
        }
        CP_COMMIT();
    };

    const int qq = lane >> 3, rr = lane & 7;
    const u32 aB = smb + (wn * 64 + (qq & 1) * 8 + rr) * 144 + (qq >> 1) * 16;
    const u32 bB = smb + AT_TILE + (wm * 32 + (qq & 1) * 8 + rr) * 144 + (qq >> 1) * 16;

    float C[4][4][4];
    #pragma unroll
    for (int i = 0; i < 4; i++)
        #pragma unroll
        for (int j = 0; j < 4; j++)
            #pragma unroll
            for (int k = 0; k < 4; k++) C[i][j][k] = 0.f;

    float v0[4], v1[4];
    #pragma unroll
    for (int ni = 0; ni < 4; ni++) {
        int nr = n0 + wn * 64 + ni * 16 + (lane >> 2);
        v0[ni] = g_v[b * HW_ + nr];
        v1[ni] = g_v[b * HW_ + nr + 8];
    }

    load_chunk(0, 0);
    load_chunk(1, 1);
    #pragma unroll
    for (int ch = 0; ch < 4; ch++) {
        if (ch < 3) { CP_WAIT(1); } else { CP_WAIT(0); }
        __syncthreads();                              // chunk ch published
        if (ch < 2) load_chunk(ch + 2, (ch + 2) % 3); // runs 2 chunks ahead

        const int buf = ch % 3;
        const u32 A0 = aB + buf * AT_STG;
        const u32 B0 = bB + buf * AT_STG;
        #pragma unroll
        for (int ks = 0; ks < 4; ks++) {
            u32 ah[4][4], bh[2][4];
            #pragma unroll
            for (int ni = 0; ni < 4; ni++)
                ldmx4(ah[ni], A0 + ks * 32 + ni * 16 * 144);
            #pragma unroll
            for (int p = 0; p < 2; p++)
                ldmx4(bh[p], B0 + ks * 32 + p * 16 * 144);
            #pragma unroll
            for (int ni = 0; ni < 4; ni++)
                #pragma unroll
                for (int mj = 0; mj < 4; mj++) {
                    const int p = mj >> 1, w = mj & 1;
                    mma_f16(C[ni][mj], ah[ni], bh[p][w], bh[p][w + 2]);
                }
        }
    }

    float dsum[4][2] = {}, nsum[4][2] = {};
    #pragma unroll
    for (int ni = 0; ni < 4; ni++)
        #pragma unroll
        for (int mj = 0; mj < 4; mj++) {
            float e0 = exp_poly(C[ni][mj][0]);
            float e1 = exp_poly(C[ni][mj][1]);
            float e2 = exp_poly(C[ni][mj][2]);
            float e3 = exp_poly(C[ni][mj][3]);
            dsum[mj][0] += e0 + e2;
            dsum[mj][1] += e1 + e3;
            nsum[mj][0] = fmaf(v0[ni], e0, fmaf(v1[ni], e2, nsum[mj][0]));
            nsum[mj][1] = fmaf(v0[ni], e1, fmaf(v1[ni], e3, nsum[mj][1]));
        }
    #pragma unroll
    for (int mj = 0; mj < 4; mj++)
        #pragma unroll
        for (int h = 0; h < 2; h++) {
            #pragma unroll
            for (int msk = 4; msk <= 16; msk <<= 1) {
                dsum[mj][h] += __shfl_xor_sync(0xFFFFFFFFu, dsum[mj][h], msk);
                nsum[mj][h] += __shfl_xor_sync(0xFFFFFFFFu, nsum[mj][h], msk);
            }
        }

    __syncthreads();
    float* redD = (float*)sm;
    float* redN = redD + 256;
    if (lane < 4) {
        #pragma unroll
        for (int mj = 0; mj < 4; mj++)
            #pragma unroll
            for (int h = 0; h < 2; h++) {
                int col = wm * 32 + mj * 8 + lane * 2 + h;
                redD[wn * 128 + col] = dsum[mj][h];
                redN[wn * 128 + col] = nsum[mj][h];
            }
    }
    __syncthreads();
    if (tid < 128) {
        atomicAdd(&g_pd[(size_t)b * HW_ + m0 + tid], redD[tid] + redD[128 + tid]);
        atomicAdd(&g_pn[(size_t)b * HW_ + m0 + tid], redN[tid] + redN[128 + tid]);
    }
}

// ---------------------------------------------------------------------------
// Conv (4 channels/block, register box filter, no smem):
// out[b,c,i,j] = sum_{di,dj<3} (pn/pd * x)[i+di][j+dj].
// Block handles channels c0..c0+3 of batch b; G rows (pn/pd) loaded and
// divided ONCE, reused across channels. Warp w owns output rows [4w,4w+4).
// ---------------------------------------------------------------------------
__global__ __launch_bounds__(256) void conv_kernel(
    const float* __restrict__ batch, float* __restrict__ out)
{
    const int c0 = blockIdx.x * 4, b = blockIdx.y;
    const int lane = threadIdx.x & 31, w = threadIdx.x >> 5;
    const float* pn = g_pn + b * HW_;
    const float* pd = g_pd + b * HW_;

    const int ostart = w * 4;
    const int nrows = (ostart == 28) ? 4 : 6;      // warp 7: rows 28..31 only
    const int ocount = (ostart == 28) ? 2 : 4;

    // batch-issue all loads first (independent -> high MLP)
    float xn[6], xd[6], xx[4][6];
    #pragma unroll
    for (int k = 0; k < 6; k++) {
        if (k < nrows) {
            int idx = (ostart + k) * 32 + lane;
            xn[k] = pn[idx];
            xd[k] = pd[idx];
            #pragma unroll
            for (int cc = 0; cc < 4; cc++)
                xx[cc][k] = batch[(size_t)(b * C_ + c0 + cc) * HW_ + idx];
        }
    }
    float G[6];
    #pragma unroll
    for (int k = 0; k < 6; k++)
        if (k < nrows) G[k] = __fdividef(xn[k], xd[k]);

    #pragma unroll
    for (int cc = 0; cc < 4; cc++) {
        float y[6];
        #pragma unroll
        for (int k = 0; k < 6; k++)
            if (k < nrows) y[k] = G[k] * xx[cc][k];
        float* ob = out + (size_t)(b * C_ + c0 + cc) * 900;
        #pragma unroll
        for (int k = 0; k < 4; k++) {
            if (k < ocount) {
                float vs = y[k] + y[k + 1] + y[k + 2];
                float s = vs + __shfl_down_sync(0xFFFFFFFFu, vs, 1)
                             + __shfl_down_sync(0xFFFFFFFFu, vs, 2);
                if (lane < 30) ob[(ostart + k) * 30 + lane] = s;
            }
        }
    }
}

extern "C" void kernel_launch(void* const* d_in, const int* in_sizes, int n_in,
                              void* d_out, int out_size)
{
    const float* batch   = (const float*)d_in[0];
    const float* key_w   = (const float*)d_in[1];
    const float* key_b   = (const float*)d_in[2];
    const float* query_w = (const float*)d_in[3];
    const float* query_b = (const float*)d_in[4];
    const float* value_w = (const float*)d_in[5];
    const float* value_b = (const float*)d_in[6];
    // d_in[7] = local_indices (unused: collapses analytically to 3x3 box filter)

    cudaFuncSetAttribute(proj_kernel, cudaFuncAttributeMaxDynamicSharedMemorySize, PROJ_SMEM);
    cudaFuncSetAttribute(attn_kernel, cudaFuncAttributeMaxDynamicSharedMemorySize, ATTN_SMEM);

    setup_kernel<<<512, 256>>>(key_w, query_w, key_b, query_b);
    proj_kernel<<<dim3(16, 16), 512, PROJ_SMEM>>>(batch, value_w, value_b);
    attn_kernel<<<dim3(8, 16, NSPLIT), 256, ATTN_SMEM>>>();
    conv_kernel<<<dim3(64, 16), 256>>>(batch, (float*)d_out);
}